// round 9
// baseline (speedup 1.0000x reference)
#include <cuda_runtime.h>
#include <cstdint>
#include <cstddef>

// Problem dimensions (fixed by the dataset; grid sizes derived from in_sizes)
#define HDIM 64
#define SDIM 256
#define ADIM 18
#define MAXB 1024
#define MAXN 200000

// ---------------- scratch (device globals: allocation-free) ----------------
__device__ float g_scores[(size_t)MAXB * MAXN];   // ~800 MB score matrix
__device__ float g_h[MAXB * HDIM];
__device__ float g_hsq[MAXB];
__device__ float g_ksq[MAXN];

// ---------------- Kernel 1: MLP (h, policy, hsq) ----------------
__global__ void __launch_bounds__(SDIM) mlp_kernel(
    const float* __restrict__ x, const float* __restrict__ W1,
    const float* __restrict__ b1, const float* __restrict__ Wp,
    const float* __restrict__ bp, float* __restrict__ out, int B)
{
    __shared__ float xs[SDIM];
    __shared__ float hs[HDIM];
    __shared__ float ps[4][HDIM];
    int row = blockIdx.x;
    int t = threadIdx.x;

    xs[t] = x[(size_t)row * SDIM + t];
    __syncthreads();

    int j = t & 63;
    int part = t >> 6;               // 4 k-partitions of 64
    const float* w = W1 + (size_t)(part * 64) * HDIM + j;
    const float* xp = xs + part * 64;
    float acc = 0.f;
#pragma unroll 8
    for (int k = 0; k < 64; k++) acc = fmaf(xp[k], w[(size_t)k * HDIM], acc);
    ps[part][j] = acc;
    __syncthreads();

    if (t < HDIM) {
        float h = ps[0][t] + ps[1][t] + ps[2][t] + ps[3][t] + b1[t];
        h = fmaxf(h, 0.f);
        hs[t] = h;
        g_h[row * HDIM + t] = h;
        // h region of output: after policy [B,A] and value [B,1]
        out[(size_t)B * (ADIM + 1) + (size_t)row * HDIM + t] = h;
        ps[0][t] = h * h;
    }
    __syncthreads();

    if (t == 0) {
        float s = 0.f;
        for (int i = 0; i < HDIM; i++) s += ps[0][i];
        g_hsq[row] = s;
    }
    if (t < ADIM) {
        float p = bp[t];
#pragma unroll
        for (int jj = 0; jj < HDIM; jj++) p = fmaf(hs[jj], Wp[jj * ADIM + t], p);
        out[(size_t)row * ADIM + t] = p;
    }
}

// ---------------- Kernel 2: key squared norms ----------------
__global__ void ksq_kernel(const float* __restrict__ Kmem, int N)
{
    int n = blockIdx.x * 256 + threadIdx.x;
    if (n < N) {
        const float4* kr = reinterpret_cast<const float4*>(Kmem + (size_t)n * HDIM);
        float s = 0.f;
#pragma unroll
        for (int i = 0; i < HDIM / 4; i++) {
            float4 v = kr[i];
            s = fmaf(v.x, v.x, s); s = fmaf(v.y, v.y, s);
            s = fmaf(v.z, v.z, s); s = fmaf(v.w, v.w, s);
        }
        g_ksq[n] = s;
    }
}

// ---------------- Kernel 3: fp32 score GEMM ----------------
// score[b][n] = h_b . k_n - 0.5*||k_n||^2   (argmax score == argmin distance)
#define TBm 64     // query rows per block
#define TNn 128    // keys per block
#define HPp 68     // Hst pitch (floats), 16B aligned, padded
#define KPp 132    // Kst pitch (floats), 16B aligned, padded
#define GEMM_SMEM ((HDIM * HPp + HDIM * KPp) * 4)

__global__ void __launch_bounds__(256) gemm_kernel(
    const float* __restrict__ Kmem, int B, int N)
{
    extern __shared__ float sm[];
    float* Hst = sm;                  // [HDIM][HPp] k-major
    float* Kst = sm + HDIM * HPp;     // [HDIM][KPp] k-major
    int tid = threadIdx.x;
    int nBase = blockIdx.x * TNn;
    int rowBase = blockIdx.y * TBm;

    // load H tile (64x64), transposed to k-major
    for (int e = tid; e < TBm * HDIM; e += 256) {
        int r = e >> 6, c = e & 63;
        Hst[c * HPp + r] = g_h[(rowBase + r) * HDIM + c];
    }
    // load K tile (128x64), transposed to k-major, zero-pad past N
    for (int e = tid; e < TNn * HDIM; e += 256) {
        int n = e >> 6, c = e & 63;
        int gn = nBase + n;
        Kst[c * KPp + n] = (gn < N) ? Kmem[(size_t)gn * HDIM + c] : 0.f;
    }
    __syncthreads();

    int tx = tid & 15, ty = tid >> 4;    // 16 x 16 thread grid
    int r0 = tx * 4, n0 = ty * 8;        // 4x8 register tile

    float acc[4][8];
#pragma unroll
    for (int i = 0; i < 4; i++)
#pragma unroll
        for (int jj = 0; jj < 8; jj++) acc[i][jj] = 0.f;

#pragma unroll 16
    for (int kk = 0; kk < HDIM; kk++) {
        float4 a = *reinterpret_cast<const float4*>(Hst + kk * HPp + r0);
        float4 p = *reinterpret_cast<const float4*>(Kst + kk * KPp + n0);
        float4 q = *reinterpret_cast<const float4*>(Kst + kk * KPp + n0 + 4);
        float av[4] = {a.x, a.y, a.z, a.w};
        float bv[8] = {p.x, p.y, p.z, p.w, q.x, q.y, q.z, q.w};
#pragma unroll
        for (int i = 0; i < 4; i++)
#pragma unroll
            for (int jj = 0; jj < 8; jj++)
                acc[i][jj] = fmaf(av[i], bv[jj], acc[i][jj]);
    }

    int gn0 = nBase + n0;
    float kq[8];
#pragma unroll
    for (int jj = 0; jj < 8; jj++) {
        int gn = gn0 + jj;
        kq[jj] = (gn < N) ? 0.5f * g_ksq[gn] : 0.f;
    }
    bool vecok = ((N & 3) == 0) && (gn0 + 8 <= N);
#pragma unroll
    for (int i = 0; i < 4; i++) {
        size_t off = (size_t)(rowBase + r0 + i) * N + gn0;
        if (vecok) {
            float4 o0, o1;
            o0.x = acc[i][0] - kq[0]; o0.y = acc[i][1] - kq[1];
            o0.z = acc[i][2] - kq[2]; o0.w = acc[i][3] - kq[3];
            o1.x = acc[i][4] - kq[4]; o1.y = acc[i][5] - kq[5];
            o1.z = acc[i][6] - kq[6]; o1.w = acc[i][7] - kq[7];
            *reinterpret_cast<float4*>(g_scores + off) = o0;
            *reinterpret_cast<float4*>(g_scores + off + 4) = o1;
        } else {
            for (int jj = 0; jj < 8; jj++)
                if (gn0 + jj < N) g_scores[off + jj] = acc[i][jj] - kq[jj];
        }
    }
}

// ---------------- Kernel 4: streaming top-50 + inverse-distance value ----------------
#define POOL 4096
#define NTSEL 512
#define BATCH 2048
#define KNB 50

__device__ __forceinline__ void bitonic_desc(float* s, int* id, int tid)
{
    for (int k = 2; k <= POOL; k <<= 1) {
        for (int j = k >> 1; j > 0; j >>= 1) {
            for (int i = tid; i < POOL; i += NTSEL) {
                int ixj = i ^ j;
                if (ixj > i) {
                    float a = s[i], b = s[ixj];
                    bool up = ((i & k) == 0);   // descending overall
                    if (up ? (a < b) : (a > b)) {
                        s[i] = b; s[ixj] = a;
                        int t = id[i]; id[i] = id[ixj]; id[ixj] = t;
                    }
                }
            }
            __syncthreads();
        }
    }
}

__global__ void __launch_bounds__(NTSEL) select_kernel(
    const float* __restrict__ vals, float* __restrict__ outv, int B, int N)
{
    __shared__ float cs[POOL];
    __shared__ int   ci[POOL];
    __shared__ int   cnt;
    __shared__ float thr;
    __shared__ float wbuf[KNB], wvbuf[KNB];

    int row = blockIdx.x;
    int tid = threadIdx.x;
    int lane = tid & 31;
    const float* Srow = g_scores + (size_t)row * N;

    if (tid == 0) { cnt = 0; thr = -3.4e38f; }
    __syncthreads();

    for (int base = 0; base < N; base += BATCH) {
        float tloc = thr;
#pragma unroll
        for (int k = 0; k < BATCH / NTSEL; k++) {
            int i = base + k * NTSEL + tid;
            float s = (i < N) ? Srow[i] : -3.4e38f;
            bool pred = (s > tloc);
            unsigned mask = __ballot_sync(0xffffffffu, pred);
            if (mask) {
                int nw = __popc(mask);
                int leader = __ffs(mask) - 1;
                int basep = 0;
                if (lane == leader) basep = atomicAdd(&cnt, nw);
                basep = __shfl_sync(0xffffffffu, basep, leader);
                if (pred) {
                    int p = basep + __popc(mask & ((1u << lane) - 1u));
                    if (p < POOL) { cs[p] = s; ci[p] = i; }
                }
            }
        }
        __syncthreads();
        int c = cnt;                          // uniform after barrier
        if (c >= POOL - BATCH) {              // compact: keep exact top-50 so far
            int cc = c > POOL ? POOL : c;
            for (int i = cc + tid; i < POOL; i += NTSEL) cs[i] = -3.4e38f;
            __syncthreads();
            bitonic_desc(cs, ci, tid);
            if (tid == 0) { thr = cs[KNB - 1]; cnt = KNB; }
            __syncthreads();
        }
    }

    // final exact selection
    int c = cnt;
    int cc = c > POOL ? POOL : c;
    for (int i = cc + tid; i < POOL; i += NTSEL) cs[i] = -3.4e38f;
    __syncthreads();
    bitonic_desc(cs, ci, tid);

    if (tid < KNB) {
        float s = cs[tid];
        float d = fmaxf(g_hsq[row] - 2.0f * s, 0.0f);   // d = hsq - 2(h.k) + ksq, clamped
        float w = 1.0f / (d + 1e-3f);
        wbuf[tid]  = w;
        wvbuf[tid] = w * vals[ci[tid]];
    }
    __syncthreads();
    if (tid == 0) {
        float ws = 0.f, wv = 0.f;
        for (int i = 0; i < KNB; i++) { ws += wbuf[i]; wv += wvbuf[i]; }
        outv[row] = wv / ws;
    }
}

// ---------------- launch ----------------
extern "C" void kernel_launch(void* const* d_in, const int* in_sizes, int n_in,
                              void* d_out, int out_size)
{
    const float* x    = (const float*)d_in[0];
    const float* W1   = (const float*)d_in[1];
    const float* b1   = (const float*)d_in[2];
    const float* Wp   = (const float*)d_in[3];
    const float* bp   = (const float*)d_in[4];
    const float* keys = (const float*)d_in[5];
    const float* vals = (const float*)d_in[6];
    float* out = (float*)d_out;

    int H = in_sizes[2];              // 64
    int S = in_sizes[1] / H;          // 256
    int B = in_sizes[0] / S;          // 1024
    int N = in_sizes[5] / H;          // 200000

    cudaFuncSetAttribute(gemm_kernel,
                         cudaFuncAttributeMaxDynamicSharedMemorySize, GEMM_SMEM);

    mlp_kernel<<<B, SDIM>>>(x, W1, b1, Wp, bp, out, B);
    ksq_kernel<<<(N + 255) / 256, 256>>>(keys, N);
    dim3 g2((N + TNn - 1) / TNn, B / TBm);
    gemm_kernel<<<g2, 256, GEMM_SMEM>>>(keys, B, N);
    // output layout: policy [B,A] | value [B,1] | h [B,H]
    select_kernel<<<B, NTSEL>>>(vals, out + (size_t)B * ADIM, B, N);
}

// round 10
// speedup vs baseline: 2.1602x; 2.1602x over previous
#include <cuda_runtime.h>
#include <cstdint>
#include <cstddef>

// Problem dimensions (fixed by the dataset; grid sizes derived from in_sizes)
#define HDIM 64
#define SDIM 256
#define ADIM 18
#define MAXB 1024
#define MAXN 200000
#define NEG_INF (-3.4e38f)

// ---------------- scratch (device globals: allocation-free) ----------------
__device__ float g_scores[(size_t)MAXB * MAXN];                      // ~800 MB
__device__ float g_blockmax[(size_t)MAXB * ((MAXN + 127) / 128)];    // ~6.4 MB
__device__ float g_h[MAXB * HDIM];
__device__ float g_hsq[MAXB];
__device__ float g_ksq[MAXN];

// ---------------- Kernel 1: MLP (h, policy, hsq) ----------------
__global__ void __launch_bounds__(SDIM) mlp_kernel(
    const float* __restrict__ x, const float* __restrict__ W1,
    const float* __restrict__ b1, const float* __restrict__ Wp,
    const float* __restrict__ bp, float* __restrict__ out, int B)
{
    __shared__ float xs[SDIM];
    __shared__ float hs[HDIM];
    __shared__ float ps[4][HDIM];
    int row = blockIdx.x;
    int t = threadIdx.x;

    xs[t] = x[(size_t)row * SDIM + t];
    __syncthreads();

    int j = t & 63;
    int part = t >> 6;               // 4 k-partitions of 64
    const float* w = W1 + (size_t)(part * 64) * HDIM + j;
    const float* xp = xs + part * 64;
    float acc = 0.f;
#pragma unroll 8
    for (int k = 0; k < 64; k++) acc = fmaf(xp[k], w[(size_t)k * HDIM], acc);
    ps[part][j] = acc;
    __syncthreads();

    if (t < HDIM) {
        float h = ps[0][t] + ps[1][t] + ps[2][t] + ps[3][t] + b1[t];
        h = fmaxf(h, 0.f);
        hs[t] = h;
        g_h[row * HDIM + t] = h;
        out[(size_t)B * (ADIM + 1) + (size_t)row * HDIM + t] = h;
        ps[0][t] = h * h;
    }
    __syncthreads();

    if (t == 0) {
        float s = 0.f;
        for (int i = 0; i < HDIM; i++) s += ps[0][i];
        g_hsq[row] = s;
    }
    if (t < ADIM) {
        float p = bp[t];
#pragma unroll
        for (int jj = 0; jj < HDIM; jj++) p = fmaf(hs[jj], Wp[jj * ADIM + t], p);
        out[(size_t)row * ADIM + t] = p;
    }
}

// ---------------- Kernel 2: key squared norms ----------------
__global__ void ksq_kernel(const float* __restrict__ Kmem, int N)
{
    int n = blockIdx.x * 256 + threadIdx.x;
    if (n < N) {
        const float4* kr = reinterpret_cast<const float4*>(Kmem + (size_t)n * HDIM);
        float s = 0.f;
#pragma unroll
        for (int i = 0; i < HDIM / 4; i++) {
            float4 v = kr[i];
            s = fmaf(v.x, v.x, s); s = fmaf(v.y, v.y, s);
            s = fmaf(v.z, v.z, s); s = fmaf(v.w, v.w, s);
        }
        g_ksq[n] = s;
    }
}

// ---------------- Kernel 3: fp32 score GEMM + per-block row max ----------------
// score[b][n] = h_b . k_n - 0.5*||k_n||^2   (argmax score == argmin distance)
#define TBm 64     // query rows per block
#define TNn 128    // keys per block
#define HPp 68     // Hst pitch (floats)
#define KPp 132    // Kst pitch (floats)
#define GEMM_SMEM ((HDIM * HPp + HDIM * KPp) * 4)

__global__ void __launch_bounds__(256) gemm_kernel(
    const float* __restrict__ Kmem, int B, int N)
{
    extern __shared__ float sm[];
    float* Hst = sm;                  // [HDIM][HPp] k-major
    float* Kst = sm + HDIM * HPp;     // [HDIM][KPp] k-major
    int tid = threadIdx.x;
    int nBase = blockIdx.x * TNn;
    int rowBase = blockIdx.y * TBm;

    for (int e = tid; e < TBm * HDIM; e += 256) {
        int r = e >> 6, c = e & 63;
        Hst[c * HPp + r] = g_h[(rowBase + r) * HDIM + c];
    }
    for (int e = tid; e < TNn * HDIM; e += 256) {
        int n = e >> 6, c = e & 63;
        int gn = nBase + n;
        Kst[c * KPp + n] = (gn < N) ? Kmem[(size_t)gn * HDIM + c] : 0.f;
    }
    __syncthreads();

    int tx = tid & 15, ty = tid >> 4;    // 16 x 16 thread grid
    int r0 = tx * 4, n0 = ty * 8;        // 4x8 register tile

    float acc[4][8];
#pragma unroll
    for (int i = 0; i < 4; i++)
#pragma unroll
        for (int jj = 0; jj < 8; jj++) acc[i][jj] = 0.f;

#pragma unroll 16
    for (int kk = 0; kk < HDIM; kk++) {
        float4 a = *reinterpret_cast<const float4*>(Hst + kk * HPp + r0);
        float4 p = *reinterpret_cast<const float4*>(Kst + kk * KPp + n0);
        float4 q = *reinterpret_cast<const float4*>(Kst + kk * KPp + n0 + 4);
        float av[4] = {a.x, a.y, a.z, a.w};
        float bv[8] = {p.x, p.y, p.z, p.w, q.x, q.y, q.z, q.w};
#pragma unroll
        for (int i = 0; i < 4; i++)
#pragma unroll
            for (int jj = 0; jj < 8; jj++)
                acc[i][jj] = fmaf(av[i], bv[jj], acc[i][jj]);
    }
    __syncthreads();                  // tiles fully consumed; smem reusable

    int gn0 = nBase + n0;
    float kq[8];
#pragma unroll
    for (int jj = 0; jj < 8; jj++) {
        int gn = gn0 + jj;
        kq[jj] = (gn < N) ? 0.5f * g_ksq[gn] : 0.f;
    }

    float* red = sm;                  // [64][17] row-max partials
    bool vecok = (gn0 + 8 <= N);
#pragma unroll
    for (int i = 0; i < 4; i++) {
        float s[8];
        float rmax = NEG_INF;
#pragma unroll
        for (int jj = 0; jj < 8; jj++) {
            s[jj] = acc[i][jj] - kq[jj];
            if (gn0 + jj < N) rmax = fmaxf(rmax, s[jj]);
        }
        size_t off = (size_t)(rowBase + r0 + i) * N + gn0;
        if (vecok) {
            float4 o0 = {s[0], s[1], s[2], s[3]};
            float4 o1 = {s[4], s[5], s[6], s[7]};
            *reinterpret_cast<float4*>(g_scores + off) = o0;
            *reinterpret_cast<float4*>(g_scores + off + 4) = o1;
        } else {
            for (int jj = 0; jj < 8; jj++)
                if (gn0 + jj < N) g_scores[off + jj] = s[jj];
        }
        red[(r0 + i) * 17 + ty] = rmax;
    }
    __syncthreads();

    if (tid < TBm) {
        float m = NEG_INF;
#pragma unroll
        for (int q = 0; q < 16; q++) m = fmaxf(m, red[tid * 17 + q]);
        g_blockmax[(size_t)(rowBase + tid) * gridDim.x + blockIdx.x] = m;
    }
}

// ---------------- Kernel 4: blockmax-filtered exact top-50 ----------------
#define NTSEL 512
#define BMPAD 2048       // pow2 >= NBLK (1563)
#define POOL 8192        // hard bound: ~50 blocks * 128 = 6400 survivors max
#define BLMAX 512
#define KNB 50
#define SEL_SMEM ((BMPAD * 2 + POOL) * 4 + POOL * 4 + BLMAX * 4)

template<bool WITH_ID>
__device__ __forceinline__ void bsort_desc(float* s, int* id, int m, int tid)
{
    for (int k = 2; k <= m; k <<= 1) {
        for (int j = k >> 1; j > 0; j >>= 1) {
            for (int i = tid; i < m; i += NTSEL) {
                int x = i ^ j;
                if (x > i) {
                    float a = s[i], b = s[x];
                    bool up = ((i & k) == 0);
                    if (up ? (a < b) : (a > b)) {
                        s[i] = b; s[x] = a;
                        if (WITH_ID) { int t = id[i]; id[i] = id[x]; id[x] = t; }
                    }
                }
            }
            __syncthreads();
        }
    }
}

__global__ void __launch_bounds__(NTSEL) select_kernel(
    const float* __restrict__ vals, float* __restrict__ outv,
    int B, int N, int NBLK)
{
    extern __shared__ float smf[];
    float* bm   = smf;                 // [BMPAD] original blockmax
    float* srt  = bm + BMPAD;          // [BMPAD] sort copy
    float* ps   = srt + BMPAD;         // [POOL] candidate scores
    int*   pi   = (int*)(ps + POOL);   // [POOL] candidate ids
    int*   blist = pi + POOL;          // [BLMAX]
    __shared__ int cnt, bcnt;
    __shared__ float wbuf[KNB], wvbuf[KNB];

    int row = blockIdx.x;
    int tid = threadIdx.x;
    int lane = tid & 31;
    int wid = tid >> 5;
    const float* Srow = g_scores + (size_t)row * N;
    const float* BMrow = g_blockmax + (size_t)row * NBLK;

    if (tid == 0) { cnt = 0; bcnt = 0; }
    for (int j = tid; j < BMPAD; j += NTSEL) {
        float v = (j < NBLK) ? BMrow[j] : NEG_INF;
        bm[j] = v; srt[j] = v;
    }
    __syncthreads();

    // T = 50th-largest blockmax; provably T <= s50 (exact filter threshold)
    bsort_desc<false>(srt, nullptr, BMPAD, tid);
    float T = srt[KNB - 1];

    // compact surviving block list (expected ~50 blocks)
    for (int j = tid; j < BMPAD; j += NTSEL) {
        bool pred = (j < NBLK) && (bm[j] >= T);
        unsigned mask = __ballot_sync(0xffffffffu, pred);
        if (mask) {
            int leader = __ffs(mask) - 1;
            int basep = 0;
            if (lane == leader) basep = atomicAdd(&bcnt, __popc(mask));
            basep = __shfl_sync(0xffffffffu, basep, leader);
            if (pred) {
                int p = basep + __popc(mask & ((1u << lane) - 1u));
                if (p < BLMAX) blist[p] = j;
            }
        }
    }
    __syncthreads();
    int nb = bcnt < BLMAX ? bcnt : BLMAX;

    // scan surviving blocks (128 scores each), keep elements >= T
    for (int b = wid; b < nb; b += NTSEL / 32) {
        int base = blist[b] * TNn;
#pragma unroll
        for (int q = 0; q < TNn / 32; q++) {
            int i = base + q * 32 + lane;
            float s = (i < N) ? Srow[i] : NEG_INF;
            bool pred = (s >= T);
            unsigned mask = __ballot_sync(0xffffffffu, pred);
            if (mask) {
                int leader = __ffs(mask) - 1;
                int basep = 0;
                if (lane == leader) basep = atomicAdd(&cnt, __popc(mask));
                basep = __shfl_sync(0xffffffffu, basep, leader);
                if (pred) {
                    int p = basep + __popc(mask & ((1u << lane) - 1u));
                    if (p < POOL) { ps[p] = s; pi[p] = i; }
                }
            }
        }
    }
    __syncthreads();

    int c = cnt < POOL ? cnt : POOL;   // guaranteed c >= 50
    int m = 64;
    while (m < c) m <<= 1;             // uniform across block
    for (int i = c + tid; i < m; i += NTSEL) { ps[i] = NEG_INF; pi[i] = 0; }
    __syncthreads();
    bsort_desc<true>(ps, pi, m, tid);

    if (tid < KNB) {
        float s = ps[tid];
        float d = fmaxf(g_hsq[row] - 2.0f * s, 0.0f);
        float w = 1.0f / (d + 1e-3f);
        wbuf[tid]  = w;
        wvbuf[tid] = w * vals[pi[tid]];
    }
    __syncthreads();
    if (tid == 0) {
        float ws = 0.f, wv = 0.f;
#pragma unroll
        for (int i = 0; i < KNB; i++) { ws += wbuf[i]; wv += wvbuf[i]; }
        outv[row] = wv / ws;
    }
}

// ---------------- launch ----------------
extern "C" void kernel_launch(void* const* d_in, const int* in_sizes, int n_in,
                              void* d_out, int out_size)
{
    const float* x    = (const float*)d_in[0];
    const float* W1   = (const float*)d_in[1];
    const float* b1   = (const float*)d_in[2];
    const float* Wp   = (const float*)d_in[3];
    const float* bp   = (const float*)d_in[4];
    const float* keys = (const float*)d_in[5];
    const float* vals = (const float*)d_in[6];
    float* out = (float*)d_out;

    int H = in_sizes[2];              // 64
    int S = in_sizes[1] / H;          // 256
    int B = in_sizes[0] / S;          // 1024
    int N = in_sizes[5] / H;          // 200000
    int NBLK = (N + TNn - 1) / TNn;   // 1563

    cudaFuncSetAttribute(gemm_kernel,
                         cudaFuncAttributeMaxDynamicSharedMemorySize, GEMM_SMEM);
    cudaFuncSetAttribute(select_kernel,
                         cudaFuncAttributeMaxDynamicSharedMemorySize, SEL_SMEM);

    mlp_kernel<<<B, SDIM>>>(x, W1, b1, Wp, bp, out, B);
    ksq_kernel<<<(N + 255) / 256, 256>>>(keys, N);
    dim3 g2(NBLK, B / TBm);
    gemm_kernel<<<g2, 256, GEMM_SMEM>>>(keys, B, N);
    // output layout: policy [B,A] | value [B,1] | h [B,H]
    select_kernel<<<B, NTSEL, SEL_SMEM>>>(vals, out + (size_t)B * ADIM, B, N, NBLK);
}

// round 11
// speedup vs baseline: 2.1605x; 1.0002x over previous
#include <cuda_runtime.h>
#include <cstdint>
#include <cstddef>

// Problem dimensions (fixed by the dataset; grid sizes derived from in_sizes)
#define HDIM 64
#define SDIM 256
#define ADIM 18
#define MAXB 1024
#define MAXN 200000
#define NEG_INF (-3.4e38f)

// ---------------- scratch (device globals: allocation-free) ----------------
__device__ float g_scores[(size_t)MAXB * MAXN];                      // ~800 MB
__device__ float g_blockmax[(size_t)MAXB * ((MAXN + 127) / 128)];    // ~6.4 MB
__device__ float g_h[MAXB * HDIM];
__device__ float g_hsq[MAXB];
__device__ float g_ksq[MAXN];

// ---------------- Kernel 1: MLP (h, policy, hsq) ----------------
__global__ void __launch_bounds__(SDIM) mlp_kernel(
    const float* __restrict__ x, const float* __restrict__ W1,
    const float* __restrict__ b1, const float* __restrict__ Wp,
    const float* __restrict__ bp, float* __restrict__ out, int B)
{
    __shared__ float xs[SDIM];
    __shared__ float hs[HDIM];
    __shared__ float ps[4][HDIM];
    int row = blockIdx.x;
    int t = threadIdx.x;

    xs[t] = x[(size_t)row * SDIM + t];
    __syncthreads();

    int j = t & 63;
    int part = t >> 6;               // 4 k-partitions of 64
    const float* w = W1 + (size_t)(part * 64) * HDIM + j;
    const float* xp = xs + part * 64;
    float acc = 0.f;
#pragma unroll 8
    for (int k = 0; k < 64; k++) acc = fmaf(xp[k], w[(size_t)k * HDIM], acc);
    ps[part][j] = acc;
    __syncthreads();

    if (t < HDIM) {
        float h = ps[0][t] + ps[1][t] + ps[2][t] + ps[3][t] + b1[t];
        h = fmaxf(h, 0.f);
        hs[t] = h;
        g_h[row * HDIM + t] = h;
        out[(size_t)B * (ADIM + 1) + (size_t)row * HDIM + t] = h;
        ps[0][t] = h * h;
    }
    __syncthreads();

    if (t == 0) {
        float s = 0.f;
        for (int i = 0; i < HDIM; i++) s += ps[0][i];
        g_hsq[row] = s;
    }
    if (t < ADIM) {
        float p = bp[t];
#pragma unroll
        for (int jj = 0; jj < HDIM; jj++) p = fmaf(hs[jj], Wp[jj * ADIM + t], p);
        out[(size_t)row * ADIM + t] = p;
    }
}

// ---------------- Kernel 2: key squared norms ----------------
__global__ void ksq_kernel(const float* __restrict__ Kmem, int N)
{
    int n = blockIdx.x * 256 + threadIdx.x;
    if (n < N) {
        const float4* kr = reinterpret_cast<const float4*>(Kmem + (size_t)n * HDIM);
        float s = 0.f;
#pragma unroll
        for (int i = 0; i < HDIM / 4; i++) {
            float4 v = kr[i];
            s = fmaf(v.x, v.x, s); s = fmaf(v.y, v.y, s);
            s = fmaf(v.z, v.z, s); s = fmaf(v.w, v.w, s);
        }
        g_ksq[n] = s;
    }
}

// ---------------- Kernel 3: fp32 score GEMM + per-block row max ----------------
// score[b][n] = h_b . k_n - 0.5*||k_n||^2   (argmax score == argmin distance)
#define TBm 64     // query rows per block
#define TNn 128    // keys per block
#define HPp 68     // Hst pitch (floats)
#define KPp 132    // Kst pitch (floats)
#define GEMM_SMEM ((HDIM * HPp + HDIM * KPp) * 4)

__global__ void __launch_bounds__(256) gemm_kernel(
    const float* __restrict__ Kmem, int B, int N)
{
    extern __shared__ float sm[];
    float* Hst = sm;                  // [HDIM][HPp] k-major
    float* Kst = sm + HDIM * HPp;     // [HDIM][KPp] k-major
    int tid = threadIdx.x;
    int nBase = blockIdx.x * TNn;
    int rowBase = blockIdx.y * TBm;

    for (int e = tid; e < TBm * HDIM; e += 256) {
        int r = e >> 6, c = e & 63;
        Hst[c * HPp + r] = g_h[(rowBase + r) * HDIM + c];
    }
    for (int e = tid; e < TNn * HDIM; e += 256) {
        int n = e >> 6, c = e & 63;
        int gn = nBase + n;
        Kst[c * KPp + n] = (gn < N) ? Kmem[(size_t)gn * HDIM + c] : 0.f;
    }
    __syncthreads();

    int tx = tid & 15, ty = tid >> 4;    // 16 x 16 thread grid
    int r0 = tx * 4, n0 = ty * 8;        // 4x8 register tile

    float acc[4][8];
#pragma unroll
    for (int i = 0; i < 4; i++)
#pragma unroll
        for (int jj = 0; jj < 8; jj++) acc[i][jj] = 0.f;

#pragma unroll 16
    for (int kk = 0; kk < HDIM; kk++) {
        float4 a = *reinterpret_cast<const float4*>(Hst + kk * HPp + r0);
        float4 p = *reinterpret_cast<const float4*>(Kst + kk * KPp + n0);
        float4 q = *reinterpret_cast<const float4*>(Kst + kk * KPp + n0 + 4);
        float av[4] = {a.x, a.y, a.z, a.w};
        float bv[8] = {p.x, p.y, p.z, p.w, q.x, q.y, q.z, q.w};
#pragma unroll
        for (int i = 0; i < 4; i++)
#pragma unroll
            for (int jj = 0; jj < 8; jj++)
                acc[i][jj] = fmaf(av[i], bv[jj], acc[i][jj]);
    }
    __syncthreads();                  // tiles fully consumed; smem reusable

    int gn0 = nBase + n0;
    float kq[8];
#pragma unroll
    for (int jj = 0; jj < 8; jj++) {
        int gn = gn0 + jj;
        kq[jj] = (gn < N) ? 0.5f * g_ksq[gn] : 0.f;
    }

    float* red = sm;                  // [64][17] row-max partials
    bool vecok = (gn0 + 8 <= N);
#pragma unroll
    for (int i = 0; i < 4; i++) {
        float s[8];
        float rmax = NEG_INF;
#pragma unroll
        for (int jj = 0; jj < 8; jj++) {
            s[jj] = acc[i][jj] - kq[jj];
            if (gn0 + jj < N) rmax = fmaxf(rmax, s[jj]);
        }
        size_t off = (size_t)(rowBase + r0 + i) * N + gn0;
        if (vecok) {
            float4 o0 = {s[0], s[1], s[2], s[3]};
            float4 o1 = {s[4], s[5], s[6], s[7]};
            *reinterpret_cast<float4*>(g_scores + off) = o0;
            *reinterpret_cast<float4*>(g_scores + off + 4) = o1;
        } else {
            for (int jj = 0; jj < 8; jj++)
                if (gn0 + jj < N) g_scores[off + jj] = s[jj];
        }
        red[(r0 + i) * 17 + ty] = rmax;
    }
    __syncthreads();

    if (tid < TBm) {
        float m = NEG_INF;
#pragma unroll
        for (int q = 0; q < 16; q++) m = fmaxf(m, red[tid * 17 + q]);
        g_blockmax[(size_t)(rowBase + tid) * gridDim.x + blockIdx.x] = m;
    }
}

// ---------------- Kernel 4: blockmax-filtered exact top-50 ----------------
#define NTSEL 512
#define BMPAD 2048       // pow2 >= NBLK (1563)
#define POOL 8192        // hard bound: ~50 blocks * 128 = 6400 survivors max
#define BLMAX 512
#define KNB 50
#define SEL_SMEM ((BMPAD * 2 + POOL) * 4 + POOL * 4 + BLMAX * 4)

template<bool WITH_ID>
__device__ __forceinline__ void bsort_desc(float* s, int* id, int m, int tid)
{
    for (int k = 2; k <= m; k <<= 1) {
        for (int j = k >> 1; j > 0; j >>= 1) {
            for (int i = tid; i < m; i += NTSEL) {
                int x = i ^ j;
                if (x > i) {
                    float a = s[i], b = s[x];
                    bool up = ((i & k) == 0);
                    if (up ? (a < b) : (a > b)) {
                        s[i] = b; s[x] = a;
                        if (WITH_ID) { int t = id[i]; id[i] = id[x]; id[x] = t; }
                    }
                }
            }
            __syncthreads();
        }
    }
}

__global__ void __launch_bounds__(NTSEL) select_kernel(
    const float* __restrict__ vals, float* __restrict__ outv,
    int B, int N, int NBLK)
{
    extern __shared__ float smf[];
    float* bm   = smf;                 // [BMPAD] original blockmax
    float* srt  = bm + BMPAD;          // [BMPAD] sort copy
    float* ps   = srt + BMPAD;         // [POOL] candidate scores
    int*   pi   = (int*)(ps + POOL);   // [POOL] candidate ids
    int*   blist = pi + POOL;          // [BLMAX]
    __shared__ int cnt, bcnt;
    __shared__ float wbuf[KNB], wvbuf[KNB];

    int row = blockIdx.x;
    int tid = threadIdx.x;
    int lane = tid & 31;
    int wid = tid >> 5;
    const float* Srow = g_scores + (size_t)row * N;
    const float* BMrow = g_blockmax + (size_t)row * NBLK;

    if (tid == 0) { cnt = 0; bcnt = 0; }
    for (int j = tid; j < BMPAD; j += NTSEL) {
        float v = (j < NBLK) ? BMrow[j] : NEG_INF;
        bm[j] = v; srt[j] = v;
    }
    __syncthreads();

    // T = 50th-largest blockmax; provably T <= s50 (exact filter threshold)
    bsort_desc<false>(srt, nullptr, BMPAD, tid);
    float T = srt[KNB - 1];

    // compact surviving block list (expected ~50 blocks)
    for (int j = tid; j < BMPAD; j += NTSEL) {
        bool pred = (j < NBLK) && (bm[j] >= T);
        unsigned mask = __ballot_sync(0xffffffffu, pred);
        if (mask) {
            int leader = __ffs(mask) - 1;
            int basep = 0;
            if (lane == leader) basep = atomicAdd(&bcnt, __popc(mask));
            basep = __shfl_sync(0xffffffffu, basep, leader);
            if (pred) {
                int p = basep + __popc(mask & ((1u << lane) - 1u));
                if (p < BLMAX) blist[p] = j;
            }
        }
    }
    __syncthreads();
    int nb = bcnt < BLMAX ? bcnt : BLMAX;

    // scan surviving blocks (128 scores each), keep elements >= T
    for (int b = wid; b < nb; b += NTSEL / 32) {
        int base = blist[b] * TNn;
#pragma unroll
        for (int q = 0; q < TNn / 32; q++) {
            int i = base + q * 32 + lane;
            float s = (i < N) ? Srow[i] : NEG_INF;
            bool pred = (s >= T);
            unsigned mask = __ballot_sync(0xffffffffu, pred);
            if (mask) {
                int leader = __ffs(mask) - 1;
                int basep = 0;
                if (lane == leader) basep = atomicAdd(&cnt, __popc(mask));
                basep = __shfl_sync(0xffffffffu, basep, leader);
                if (pred) {
                    int p = basep + __popc(mask & ((1u << lane) - 1u));
                    if (p < POOL) { ps[p] = s; pi[p] = i; }
                }
            }
        }
    }
    __syncthreads();

    int c = cnt < POOL ? cnt : POOL;   // guaranteed c >= 50
    int m = 64;
    while (m < c) m <<= 1;             // uniform across block
    for (int i = c + tid; i < m; i += NTSEL) { ps[i] = NEG_INF; pi[i] = 0; }
    __syncthreads();
    bsort_desc<true>(ps, pi, m, tid);

    if (tid < KNB) {
        float s = ps[tid];
        float d = fmaxf(g_hsq[row] - 2.0f * s, 0.0f);
        float w = 1.0f / (d + 1e-3f);
        wbuf[tid]  = w;
        wvbuf[tid] = w * vals[pi[tid]];
    }
    __syncthreads();
    if (tid == 0) {
        float ws = 0.f, wv = 0.f;
#pragma unroll
        for (int i = 0; i < KNB; i++) { ws += wbuf[i]; wv += wvbuf[i]; }
        outv[row] = wv / ws;
    }
}

// ---------------- launch ----------------
extern "C" void kernel_launch(void* const* d_in, const int* in_sizes, int n_in,
                              void* d_out, int out_size)
{
    const float* x    = (const float*)d_in[0];
    const float* W1   = (const float*)d_in[1];
    const float* b1   = (const float*)d_in[2];
    const float* Wp   = (const float*)d_in[3];
    const float* bp   = (const float*)d_in[4];
    const float* keys = (const float*)d_in[5];
    const float* vals = (const float*)d_in[6];
    float* out = (float*)d_out;

    int H = in_sizes[2];              // 64
    int S = in_sizes[1] / H;          // 256
    int B = in_sizes[0] / S;          // 1024
    int N = in_sizes[5] / H;          // 200000
    int NBLK = (N + TNn - 1) / TNn;   // 1563

    cudaFuncSetAttribute(gemm_kernel,
                         cudaFuncAttributeMaxDynamicSharedMemorySize, GEMM_SMEM);
    cudaFuncSetAttribute(select_kernel,
                         cudaFuncAttributeMaxDynamicSharedMemorySize, SEL_SMEM);

    mlp_kernel<<<B, SDIM>>>(x, W1, b1, Wp, bp, out, B);
    ksq_kernel<<<(N + 255) / 256, 256>>>(keys, N);
    dim3 g2(NBLK, B / TBm);
    gemm_kernel<<<g2, 256, GEMM_SMEM>>>(keys, B, N);
    // output layout: policy [B,A] | value [B,1] | h [B,H]
    select_kernel<<<B, NTSEL, SEL_SMEM>>>(vals, out + (size_t)B * ADIM, B, N, NBLK);
}

// round 14
// speedup vs baseline: 7.0323x; 3.2550x over previous
#include <cuda_runtime.h>
#include <cuda_bf16.h>
#include <cstdint>
#include <cstddef>

// Problem dimensions (fixed by the dataset; grid sizes derived from in_sizes)
#define HDIM 64
#define SDIM 256
#define ADIM 18
#define MAXB 1024
#define MAXN 200000
#define MAXNBLK ((MAXN + 127) / 128)          // 1563
#define MAXNPAD (MAXNBLK * 128)               // 200064
#define NEG_INF (-3.4e38f)
#define KNB 50

// ---------------- scratch (device globals: allocation-free) ----------------
__device__ __nv_bfloat16 g_coarse[(size_t)MAXB * MAXNPAD];   // ~410 MB coarse scores
__device__ __nv_bfloat16 g_kbf[(size_t)MAXN * HDIM];         // bf16 keys
__device__ float g_blockmax[(size_t)MAXB * MAXNBLK];         // ~6.4 MB
__device__ float g_h[MAXB * HDIM];
__device__ float g_hsq[MAXB];
__device__ float g_ksq[MAXN];

__device__ __forceinline__ uint32_t smem_u32(const void* p) {
    uint32_t a;
    asm("{ .reg .u64 t; cvta.to.shared.u64 t, %1; cvt.u32.u64 %0, t; }"
        : "=r"(a) : "l"(p));
    return a;
}
__device__ __forceinline__ void ldmatrix_x4(uint32_t* r, uint32_t addr) {
    asm volatile("ldmatrix.sync.aligned.m8n8.x4.shared.b16 {%0,%1,%2,%3}, [%4];"
                 : "=r"(r[0]), "=r"(r[1]), "=r"(r[2]), "=r"(r[3]) : "r"(addr));
}
__device__ __forceinline__ void mma_bf16(float* d, const uint32_t* a,
                                         uint32_t b0, uint32_t b1) {
    asm volatile(
        "mma.sync.aligned.m16n8k16.row.col.f32.bf16.bf16.f32 "
        "{%0,%1,%2,%3}, {%4,%5,%6,%7}, {%8,%9}, {%0,%1,%2,%3};"
        : "+f"(d[0]), "+f"(d[1]), "+f"(d[2]), "+f"(d[3])
        : "r"(a[0]), "r"(a[1]), "r"(a[2]), "r"(a[3]), "r"(b0), "r"(b1));
}
#define SW128(off) ((off) ^ (((off) >> 3) & 0x70))

// ---------------- Kernel 1: MLP (h, policy, hsq) ----------------
__global__ void __launch_bounds__(SDIM) mlp_kernel(
    const float* __restrict__ x, const float* __restrict__ W1,
    const float* __restrict__ b1, const float* __restrict__ Wp,
    const float* __restrict__ bp, float* __restrict__ out, int B)
{
    __shared__ float xs[SDIM];
    __shared__ float hs[HDIM];
    __shared__ float ps[4][HDIM];
    int row = blockIdx.x;
    int t = threadIdx.x;

    xs[t] = x[(size_t)row * SDIM + t];
    __syncthreads();

    int j = t & 63;
    int part = t >> 6;
    const float* w = W1 + (size_t)(part * 64) * HDIM + j;
    const float* xp = xs + part * 64;
    float acc = 0.f;
#pragma unroll 8
    for (int k = 0; k < 64; k++) acc = fmaf(xp[k], w[(size_t)k * HDIM], acc);
    ps[part][j] = acc;
    __syncthreads();

    if (t < HDIM) {
        float h = ps[0][t] + ps[1][t] + ps[2][t] + ps[3][t] + b1[t];
        h = fmaxf(h, 0.f);
        hs[t] = h;
        g_h[row * HDIM + t] = h;
        out[(size_t)B * (ADIM + 1) + (size_t)row * HDIM + t] = h;
        ps[0][t] = h * h;
    }
    __syncthreads();

    if (t == 0) {
        float s = 0.f;
        for (int i = 0; i < HDIM; i++) s += ps[0][i];
        g_hsq[row] = s;
    }
    if (t < ADIM) {
        float p = bp[t];
#pragma unroll
        for (int jj = 0; jj < HDIM; jj++) p = fmaf(hs[jj], Wp[jj * ADIM + t], p);
        out[(size_t)row * ADIM + t] = p;
    }
}

// ---------------- Kernel 2: key squared norms ----------------
__global__ void ksq_kernel(const float* __restrict__ Kmem, int N)
{
    int n = blockIdx.x * 256 + threadIdx.x;
    if (n < N) {
        const float4* kr = reinterpret_cast<const float4*>(Kmem + (size_t)n * HDIM);
        float s = 0.f;
#pragma unroll
        for (int i = 0; i < HDIM / 4; i++) {
            float4 v = kr[i];
            s = fmaf(v.x, v.x, s); s = fmaf(v.y, v.y, s);
            s = fmaf(v.z, v.z, s); s = fmaf(v.w, v.w, s);
        }
        g_ksq[n] = s;
    }
}

// ---------------- Kernel 2b: keys fp32 -> bf16 ----------------
__global__ void kbf_kernel(const float* __restrict__ Kmem, int N)
{
    int i = blockIdx.x * 256 + threadIdx.x;
    if (i < N * (HDIM / 2)) {
        float2 v = reinterpret_cast<const float2*>(Kmem)[i];
        __nv_bfloat162 b = __float22bfloat162_rn(v);
        reinterpret_cast<__nv_bfloat162*>(g_kbf)[i] = b;
    }
}

// ---------------- Kernel 3: HMMA bf16 coarse GEMM + blockmax ----------------
// coarse[b][n] = bf16dot(h_b, k_n) - 0.5*ksq[n]  (f32 accum, stored bf16)
__global__ void __launch_bounds__(256, 2) tgemm_kernel(int B, int N, int NBLK,
                                                       int NPAD, int tilesPerCTA)
{
    __shared__ __align__(128) uint8_t sA[128 * 128];      // 128 rows x 64 bf16, SW128
    __shared__ __align__(128) uint8_t sB[128 * 128];      // 128 keys x 64 bf16, SW128
    __shared__ __align__(128) uint8_t sStage[128 * 256];  // 128 x 128 bf16 out stage
    __shared__ float sKsq[128];

    int tid = threadIdx.x, wid = tid >> 5, lane = tid & 31;
    int rowBase = blockIdx.y * 128;
    int blk0 = blockIdx.x * tilesPerCTA;
    uint32_t sA_u = smem_u32(sA), sB_u = smem_u32(sB);

    // load + convert A tile (h rows fp32 -> bf16, SW128): thread t = row t, 128B
    {
        const float4* hr = reinterpret_cast<const float4*>(
            g_h + (size_t)(rowBase + (tid & 127)) * HDIM);
        if (tid < 128) {
#pragma unroll
            for (int i = 0; i < 8; i++) {
                float4 a = hr[2 * i], b = hr[2 * i + 1];
                uint32_t q[4];
                __nv_bfloat162 t0 = __float22bfloat162_rn(make_float2(a.x, a.y));
                __nv_bfloat162 t1 = __float22bfloat162_rn(make_float2(a.z, a.w));
                __nv_bfloat162 t2 = __float22bfloat162_rn(make_float2(b.x, b.y));
                __nv_bfloat162 t3 = __float22bfloat162_rn(make_float2(b.z, b.w));
                q[0] = *(uint32_t*)&t0; q[1] = *(uint32_t*)&t1;
                q[2] = *(uint32_t*)&t2; q[3] = *(uint32_t*)&t3;
                unsigned off = tid * 128 + i * 16;
                *(uint4*)(&sA[SW128(off)]) = *(uint4*)q;
            }
        }
    }
    __syncthreads();

    // preload A fragments (rows w*16..w*16+15, all 4 K16 chunks) — fixed per CTA
    uint32_t af[4][4];
    {
        int rA = wid * 16 + (lane & 15);
#pragma unroll
        for (int kc = 0; kc < 4; kc++) {
            unsigned off = rA * 128 + kc * 32 + (lane & 16);
            ldmatrix_x4(af[kc], sA_u + SW128(off));
        }
    }

    for (int it = 0; it < tilesPerCTA; it++) {
        int blk = blk0 + it;
        if (blk >= NBLK) break;
        int nBase = blk * 128;

        // load B tile: thread t covers key n=t>>1, half=(t&1) (32 bf16 = 64B)
        {
            int n = tid >> 1, half = tid & 1;
            int gn = nBase + n;
            if (gn < N) {
                const uint4* kr = reinterpret_cast<const uint4*>(
                    g_kbf + (size_t)gn * HDIM + half * 32);
#pragma unroll
                for (int i = 0; i < 4; i++) {
                    unsigned off = n * 128 + half * 64 + i * 16;
                    *(uint4*)(&sB[SW128(off)]) = kr[i];
                }
            } else {
                uint4 z = make_uint4(0, 0, 0, 0);
#pragma unroll
                for (int i = 0; i < 4; i++) {
                    unsigned off = n * 128 + half * 64 + i * 16;
                    *(uint4*)(&sB[SW128(off)]) = z;
                }
            }
            if (tid < 128) sKsq[tid] = (nBase + tid < N) ? g_ksq[nBase + tid] : 0.f;
        }
        __syncthreads();

        // 16 n-tiles x 4 K16 chunks of m16n8k16
        float acc[16][4];
#pragma unroll
        for (int nt = 0; nt < 16; nt++)
#pragma unroll
            for (int q = 0; q < 4; q++) acc[nt][q] = 0.f;

        int rB = (lane & 7) + ((lane & 16) ? 8 : 0);
        int cB = (lane & 8) ? 16 : 0;
#pragma unroll
        for (int kc = 0; kc < 4; kc++) {
#pragma unroll
            for (int p = 0; p < 8; p++) {           // n-tile pairs
                uint32_t bfr[4];
                unsigned off = (p * 16 + rB) * 128 + kc * 32 + cB;
                ldmatrix_x4(bfr, sB_u + SW128(off));
                mma_bf16(acc[2 * p],     af[kc], bfr[0], bfr[1]);
                mma_bf16(acc[2 * p + 1], af[kc], bfr[2], bfr[3]);
            }
        }

        // epilogue: score = acc - 0.5*ksq, blockmax, pack bf16 into stage
        int r_lo = wid * 16 + (lane >> 2);
        int r_hi = r_lo + 8;
        float rmax_lo = NEG_INF, rmax_hi = NEG_INF;
#pragma unroll
        for (int nt = 0; nt < 16; nt++) {
            int c = nt * 8 + (lane & 3) * 2;
            float2 kq = *reinterpret_cast<const float2*>(&sKsq[c]);
            float s0 = acc[nt][0] - 0.5f * kq.x;
            float s1 = acc[nt][1] - 0.5f * kq.y;
            float s2 = acc[nt][2] - 0.5f * kq.x;
            float s3 = acc[nt][3] - 0.5f * kq.y;
            if (nBase + c     >= N) { s0 = NEG_INF; s2 = NEG_INF; }
            if (nBase + c + 1 >= N) { s1 = NEG_INF; s3 = NEG_INF; }
            rmax_lo = fmaxf(rmax_lo, fmaxf(s0, s1));
            rmax_hi = fmaxf(rmax_hi, fmaxf(s2, s3));
            __nv_bfloat162 p0 = __float22bfloat162_rn(make_float2(s0, s1));
            __nv_bfloat162 p1 = __float22bfloat162_rn(make_float2(s2, s3));
            unsigned o0 = r_lo * 256 + c * 2;
            unsigned o1 = r_hi * 256 + c * 2;
            *(uint32_t*)(&sStage[o0 ^ ((unsigned)(r_lo & 7) << 4)]) = *(uint32_t*)&p0;
            *(uint32_t*)(&sStage[o1 ^ ((unsigned)(r_hi & 7) << 4)]) = *(uint32_t*)&p1;
        }
        // quad-reduce row maxima (lanes l, l^1, l^2 share the row)
#pragma unroll
        for (int o = 1; o <= 2; o <<= 1) {
            rmax_lo = fmaxf(rmax_lo, __shfl_xor_sync(0xffffffffu, rmax_lo, o));
            rmax_hi = fmaxf(rmax_hi, __shfl_xor_sync(0xffffffffu, rmax_hi, o));
        }
        if ((lane & 3) == 0) {
            g_blockmax[(size_t)(rowBase + r_lo) * NBLK + blk] = rmax_lo;
            g_blockmax[(size_t)(rowBase + r_hi) * NBLK + blk] = rmax_hi;
        }
        __syncthreads();

        // coalesced copy stage -> g_coarse (128 rows x 256B)
        for (int j = tid; j < 128 * 16; j += 256) {
            int row = j >> 4, c16 = j & 15;
            unsigned off = (row * 256 + c16 * 16) ^ ((unsigned)(row & 7) << 4);
            uint4 v = *(uint4*)(&sStage[off]);
            *reinterpret_cast<uint4*>(
                g_coarse + (size_t)(rowBase + row) * NPAD + nBase + c16 * 8) = v;
        }
        __syncthreads();
    }
}

// ---------------- Kernel 4: radix-threshold + exact refine top-50 ----------------
#define NTS 256
#define POOL2 1024
#define BLMAX 1024
#define MARGIN 1.5f      // covers bf16 input rounding + bf16 coarse storage error

__device__ __forceinline__ void bsort_desc(float* s, int* id, int m, int tid)
{
    for (int k = 2; k <= m; k <<= 1) {
        for (int j = k >> 1; j > 0; j >>= 1) {
            for (int i = tid; i < m; i += NTS) {
                int x = i ^ j;
                if (x > i) {
                    float a = s[i], b = s[x];
                    bool up = ((i & k) == 0);
                    if (up ? (a < b) : (a > b)) {
                        s[i] = b; s[x] = a;
                        int t = id[i]; id[i] = id[x]; id[x] = t;
                    }
                }
            }
            __syncthreads();
        }
    }
}

__global__ void __launch_bounds__(NTS) select2_kernel(
    const float* __restrict__ keys, const float* __restrict__ vals,
    float* __restrict__ outv, int B, int N, int NBLK, int NPAD)
{
    __shared__ unsigned ubm[MAXNBLK + 1];
    __shared__ int hist[256];
    __shared__ int blist[BLMAX];
    __shared__ float ps[POOL2];
    __shared__ int pi[POOL2];
    __shared__ __align__(8) float hrow[HDIM];
    __shared__ float wbuf[KNB], wvbuf[KNB];
    __shared__ unsigned sPfx;
    __shared__ int sK, bcnt, cnt;

    int row = blockIdx.x;
    int tid = threadIdx.x, lane = tid & 31, wid = tid >> 5;
    const float* BMrow = g_blockmax + (size_t)row * NBLK;
    const __nv_bfloat16* Crow = g_coarse + (size_t)row * NPAD;

    if (tid == 0) { sPfx = 0; sK = KNB; bcnt = 0; cnt = 0; }
    if (tid < HDIM) hrow[tid] = g_h[row * HDIM + tid];
    for (int j = tid; j < NBLK; j += NTS) {
        unsigned b = __float_as_uint(BMrow[j]);
        ubm[j] = (b & 0x80000000u) ? ~b : (b | 0x80000000u);
    }
    __syncthreads();

    // exact 50th-largest blockmax via 4-pass radix select
    for (int p = 3; p >= 0; p--) {
        for (int i = tid; i < 256; i += NTS) hist[i] = 0;
        __syncthreads();
        unsigned pfx = sPfx;
        int sh = p * 8;
        unsigned maskhi = (p == 3) ? 0u : (0xFFFFFFFFu << (8 * (p + 1)));
        for (int j = tid; j < NBLK; j += NTS) {
            unsigned u = ubm[j];
            if ((u & maskhi) == pfx) atomicAdd(&hist[(u >> sh) & 255], 1);
        }
        __syncthreads();
        if (tid == 0) {
            int K = sK, cum = 0;
            for (int b2 = 255; b2 >= 0; b2--) {
                int c = hist[b2];
                if (cum + c >= K) { sPfx = pfx | ((unsigned)b2 << sh); sK = K - cum; break; }
                cum += c;
            }
        }
        __syncthreads();
    }
    unsigned Tu = sPfx;
    float Tf = (Tu & 0x80000000u) ? __uint_as_float(Tu & 0x7FFFFFFFu)
                                  : __uint_as_float(~Tu);
    float Tm = Tf - MARGIN;
    unsigned tb = __float_as_uint(Tm);
    unsigned um = (tb & 0x80000000u) ? ~tb : (tb | 0x80000000u);

    // surviving block list (coarse blockmax >= Tm)
    // NOTE: loop bound padded to a multiple of NTS so every thread of every
    // warp stays in the loop for all iterations — __ballot_sync with the full
    // mask is only legal when no named lane has exited (R12 hang root cause).
    int NBLKpad = (NBLK + NTS - 1) / NTS * NTS;
    for (int j = tid; j < NBLKpad; j += NTS) {
        bool pred = (j < NBLK) && (ubm[j] >= um);
        unsigned mask = __ballot_sync(0xffffffffu, pred);
        if (mask) {
            int leader = __ffs(mask) - 1;
            int basep = 0;
            if (lane == leader) basep = atomicAdd(&bcnt, __popc(mask));
            basep = __shfl_sync(0xffffffffu, basep, leader);
            if (pred) {
                int p = basep + __popc(mask & ((1u << lane) - 1u));
                if (p < BLMAX) blist[p] = j;
            }
        }
    }
    __syncthreads();
    int nb = bcnt < BLMAX ? bcnt : BLMAX;

    // scan surviving blocks' coarse bf16 scores, collect candidate ids
    // (b-loop bound nb is CTA-uniform; each warp iterates with uniform b)
    for (int b = wid; b < nb; b += NTS / 32) {
        int base = blist[b] * 128;
#pragma unroll
        for (int q = 0; q < 4; q++) {
            int i = base + q * 32 + lane;
            float s = __bfloat162float(Crow[i]);     // padding cols are -inf
            bool pred = (s >= Tm);
            unsigned mask = __ballot_sync(0xffffffffu, pred);
            if (mask) {
                int leader = __ffs(mask) - 1;
                int basep = 0;
                if (lane == leader) basep = atomicAdd(&cnt, __popc(mask));
                basep = __shfl_sync(0xffffffffu, basep, leader);
                if (pred) {
                    int p = basep + __popc(mask & ((1u << lane) - 1u));
                    if (p < POOL2) pi[p] = i;
                }
            }
        }
    }
    __syncthreads();
    int c = cnt < POOL2 ? cnt : POOL2;

    // exact fp32 refine: warp per candidate (warp-uniform loop bound)
    for (int j = wid; j < c; j += NTS / 32) {
        int id = pi[j];
        float2 kv = reinterpret_cast<const float2*>(keys + (size_t)id * HDIM)[lane];
        float2 hv = *reinterpret_cast<const float2*>(hrow + 2 * lane);
        float d = kv.x * hv.x + kv.y * hv.y;
#pragma unroll
        for (int o = 16; o; o >>= 1) d += __shfl_xor_sync(0xffffffffu, d, o);
        if (lane == 0) ps[j] = d - 0.5f * g_ksq[id];
    }
    __syncthreads();

    int m = 64;
    while (m < c) m <<= 1;
    for (int i = c + tid; i < m; i += NTS) { ps[i] = NEG_INF; pi[i] = 0; }
    __syncthreads();
    bsort_desc(ps, pi, m, tid);

    if (tid < KNB) {
        float s = ps[tid];
        float d = fmaxf(g_hsq[row] - 2.0f * s, 0.0f);
        float w = 1.0f / (d + 1e-3f);
        wbuf[tid]  = w;
        wvbuf[tid] = w * vals[pi[tid]];
    }
    __syncthreads();
    if (tid == 0) {
        float ws = 0.f, wv = 0.f;
#pragma unroll
        for (int i = 0; i < KNB; i++) { ws += wbuf[i]; wv += wvbuf[i]; }
        outv[row] = wv / ws;
    }
}

// ---------------- launch ----------------
extern "C" void kernel_launch(void* const* d_in, const int* in_sizes, int n_in,
                              void* d_out, int out_size)
{
    const float* x    = (const float*)d_in[0];
    const float* W1   = (const float*)d_in[1];
    const float* b1   = (const float*)d_in[2];
    const float* Wp   = (const float*)d_in[3];
    const float* bp   = (const float*)d_in[4];
    const float* keys = (const float*)d_in[5];
    const float* vals = (const float*)d_in[6];
    float* out = (float*)d_out;

    int H = in_sizes[2];              // 64
    int S = in_sizes[1] / H;          // 256
    int B = in_sizes[0] / S;          // 1024
    int N = in_sizes[5] / H;          // 200000
    int NBLK = (N + 127) / 128;       // 1563
    int NPAD = NBLK * 128;            // 200064

    mlp_kernel<<<B, SDIM>>>(x, W1, b1, Wp, bp, out, B);
    ksq_kernel<<<(N + 255) / 256, 256>>>(keys, N);
    kbf_kernel<<<(N * (HDIM / 2) + 255) / 256, 256>>>(keys, N);

    int STRIPS = 37;                                  // 37*8 = 296 CTAs = 1 wave @occ2
    int tilesPerCTA = (NBLK + STRIPS - 1) / STRIPS;   // 43
    dim3 g2(STRIPS, B / 128);
    tgemm_kernel<<<g2, 256>>>(B, N, NBLK, NPAD, tilesPerCTA);

    // output layout: policy [B,A] | value [B,1] | h [B,H]
    select2_kernel<<<B, NTS>>>(keys, vals, out + (size_t)B * ADIM, B, N, NBLK, NPAD);
}

// round 15
// speedup vs baseline: 8.2269x; 1.1699x over previous
#include <cuda_runtime.h>
#include <cuda_bf16.h>
#include <cstdint>
#include <cstddef>

// Problem dimensions (fixed by the dataset; grid sizes derived from in_sizes)
#define HDIM 64
#define SDIM 256
#define ADIM 18
#define MAXB 1024
#define MAXN 200000
#define MAXNBLK ((MAXN + 127) / 128)          // 1563
#define MAXNPAD (MAXNBLK * 128)               // 200064
#define NEG_INF (-3.4e38f)
#define KNB 50

// ---------------- scratch (device globals: allocation-free) ----------------
__device__ __nv_bfloat16 g_coarse[(size_t)MAXB * MAXNPAD];   // ~410 MB coarse scores
__device__ __nv_bfloat16 g_kbf[(size_t)MAXN * HDIM];         // bf16 keys
__device__ float g_blockmax[(size_t)MAXB * MAXNBLK];         // ~6.4 MB
__device__ float g_h[MAXB * HDIM];
__device__ float g_hsq[MAXB];
__device__ float g_ksq[MAXN];

__device__ __forceinline__ uint32_t smem_u32(const void* p) {
    uint32_t a;
    asm("{ .reg .u64 t; cvta.to.shared.u64 t, %1; cvt.u32.u64 %0, t; }"
        : "=r"(a) : "l"(p));
    return a;
}
__device__ __forceinline__ void ldmatrix_x4(uint32_t* r, uint32_t addr) {
    asm volatile("ldmatrix.sync.aligned.m8n8.x4.shared.b16 {%0,%1,%2,%3}, [%4];"
                 : "=r"(r[0]), "=r"(r[1]), "=r"(r[2]), "=r"(r[3]) : "r"(addr));
}
__device__ __forceinline__ void mma_bf16(float* d, const uint32_t* a,
                                         uint32_t b0, uint32_t b1) {
    asm volatile(
        "mma.sync.aligned.m16n8k16.row.col.f32.bf16.bf16.f32 "
        "{%0,%1,%2,%3}, {%4,%5,%6,%7}, {%8,%9}, {%0,%1,%2,%3};"
        : "+f"(d[0]), "+f"(d[1]), "+f"(d[2]), "+f"(d[3])
        : "r"(a[0]), "r"(a[1]), "r"(a[2]), "r"(a[3]), "r"(b0), "r"(b1));
}
__device__ __forceinline__ void cp_async16(uint32_t dst, const void* src) {
    asm volatile("cp.async.ca.shared.global [%0], [%1], 16;"
                 :: "r"(dst), "l"(src) : "memory");
}
#define CP_COMMIT() asm volatile("cp.async.commit_group;" ::: "memory")
#define CP_WAIT(n)  asm volatile("cp.async.wait_group %0;" :: "n"(n) : "memory")
#define SW128(off) ((off) ^ (((off) >> 3) & 0x70))

// ---------------- Kernel 1: MLP (h, policy, hsq) ----------------
__global__ void __launch_bounds__(SDIM) mlp_kernel(
    const float* __restrict__ x, const float* __restrict__ W1,
    const float* __restrict__ b1, const float* __restrict__ Wp,
    const float* __restrict__ bp, float* __restrict__ out, int B)
{
    __shared__ float xs[SDIM];
    __shared__ float hs[HDIM];
    __shared__ float ps[4][HDIM];
    int row = blockIdx.x;
    int t = threadIdx.x;

    xs[t] = x[(size_t)row * SDIM + t];
    __syncthreads();

    int j = t & 63;
    int part = t >> 6;
    const float* w = W1 + (size_t)(part * 64) * HDIM + j;
    const float* xp = xs + part * 64;
    float acc = 0.f;
#pragma unroll 8
    for (int k = 0; k < 64; k++) acc = fmaf(xp[k], w[(size_t)k * HDIM], acc);
    ps[part][j] = acc;
    __syncthreads();

    if (t < HDIM) {
        float h = ps[0][t] + ps[1][t] + ps[2][t] + ps[3][t] + b1[t];
        h = fmaxf(h, 0.f);
        hs[t] = h;
        g_h[row * HDIM + t] = h;
        out[(size_t)B * (ADIM + 1) + (size_t)row * HDIM + t] = h;
        ps[0][t] = h * h;
    }
    __syncthreads();

    if (t == 0) {
        float s = 0.f;
        for (int i = 0; i < HDIM; i++) s += ps[0][i];
        g_hsq[row] = s;
    }
    if (t < ADIM) {
        float p = bp[t];
#pragma unroll
        for (int jj = 0; jj < HDIM; jj++) p = fmaf(hs[jj], Wp[jj * ADIM + t], p);
        out[(size_t)row * ADIM + t] = p;
    }
}

// ---------------- Kernel 2: keys fp32 -> bf16 + squared norms (fused) ----------------
// warp per key: lane l handles float2 l of the key (64 floats), reduces ||k||^2
__global__ void __launch_bounds__(256) kprep_kernel(const float* __restrict__ Kmem, int N)
{
    int gw = blockIdx.x * 8 + (threadIdx.x >> 5);   // key index
    int lane = threadIdx.x & 31;
    if (gw >= N) return;
    float2 v = reinterpret_cast<const float2*>(Kmem + (size_t)gw * HDIM)[lane];
    __nv_bfloat162 b = __float22bfloat162_rn(v);
    reinterpret_cast<__nv_bfloat162*>(g_kbf + (size_t)gw * HDIM)[lane] = b;
    float s = fmaf(v.x, v.x, v.y * v.y);
#pragma unroll
    for (int o = 16; o; o >>= 1) s += __shfl_xor_sync(0xffffffffu, s, o);
    if (lane == 0) g_ksq[gw] = s;
}

// ---------------- Kernel 3: HMMA bf16 coarse GEMM + blockmax (pipelined) ----------------
// coarse[b][n] = bf16dot(h_b, k_n) - 0.5*ksq[n]  (f32 accum, stored bf16)
__global__ void __launch_bounds__(256, 2) tgemm_kernel(int B, int N, int NBLK,
                                                       int NPAD, int tilesPerCTA)
{
    __shared__ __align__(1024) uint8_t sA[128 * 128];         // 128 rows x 64 bf16, SW128
    __shared__ __align__(1024) uint8_t sB[2][128 * 128];      // double-buffered B tiles
    __shared__ __align__(16) float sKsq[2][128];
    __shared__ __align__(128) uint8_t sStage[128 * 256];      // per-warp-private rows

    int tid = threadIdx.x, wid = tid >> 5, lane = tid & 31;
    int rowBase = blockIdx.y * 128;
    int blk0 = blockIdx.x * tilesPerCTA;
    uint32_t sA_u = smem_u32(sA);
    uint32_t sB_u[2] = { smem_u32(sB[0]), smem_u32(sB[1]) };
    uint32_t sK_u[2] = { smem_u32(sKsq[0]), smem_u32(sKsq[1]) };

    // cp.async prefetch of one B tile (+ksq) into buffer `buf`
    auto prefetch = [&](int blk, int buf) {
        int nBase = blk * 128;
        int n = tid >> 1, half = tid & 1;
        int gn = nBase + n; if (gn > N - 1) gn = N - 1;     // pads masked in epilogue
        const __nv_bfloat16* src = g_kbf + (size_t)gn * HDIM + half * 32;
#pragma unroll
        for (int i = 0; i < 4; i++)
            cp_async16(sB_u[buf] + SW128((unsigned)(n * 128 + half * 64 + i * 16)),
                       src + i * 8);
        if (tid < 32) {
            int cb = nBase + tid * 4; if (cb > N - 4) cb = N - 4;  // N multiple of 4
            cp_async16(sK_u[buf] + tid * 16, g_ksq + cb);
        }
        CP_COMMIT();
    };

    // load + convert A tile (h rows fp32 -> bf16, SW128): thread t = row t, 128B
    {
        const float4* hr = reinterpret_cast<const float4*>(
            g_h + (size_t)(rowBase + (tid & 127)) * HDIM);
        if (tid < 128) {
#pragma unroll
            for (int i = 0; i < 8; i++) {
                float4 a = hr[2 * i], b = hr[2 * i + 1];
                uint32_t q[4];
                __nv_bfloat162 t0 = __float22bfloat162_rn(make_float2(a.x, a.y));
                __nv_bfloat162 t1 = __float22bfloat162_rn(make_float2(a.z, a.w));
                __nv_bfloat162 t2 = __float22bfloat162_rn(make_float2(b.x, b.y));
                __nv_bfloat162 t3 = __float22bfloat162_rn(make_float2(b.z, b.w));
                q[0] = *(uint32_t*)&t0; q[1] = *(uint32_t*)&t1;
                q[2] = *(uint32_t*)&t2; q[3] = *(uint32_t*)&t3;
                unsigned off = tid * 128 + i * 16;
                *(uint4*)(&sA[SW128(off)]) = *(uint4*)q;
            }
        }
    }
    prefetch(blk0, 0);                         // tile 0 in flight
    __syncthreads();

    // preload A fragments (rows w*16..w*16+15, all 4 K16 chunks) — fixed per CTA
    uint32_t af[4][4];
    {
        int rA = wid * 16 + (lane & 15);
#pragma unroll
        for (int kc = 0; kc < 4; kc++) {
            unsigned off = rA * 128 + kc * 32 + (lane & 16);
            ldmatrix_x4(af[kc], sA_u + SW128(off));
        }
    }

    int nTiles = tilesPerCTA;
    if (blk0 + nTiles > NBLK) nTiles = NBLK - blk0;

    for (int it = 0; it < nTiles; it++) {
        int blk = blk0 + it;
        int nBase = blk * 128;
        int cur = it & 1;

        bool more = (it + 1 < nTiles);
        if (more) prefetch(blk + 1, cur ^ 1);
        if (more) { CP_WAIT(1); } else { CP_WAIT(0); }
        __syncthreads();                        // buffer `cur` visible to all

        // 16 n-tiles x 4 K16 chunks of m16n8k16
        float acc[16][4];
#pragma unroll
        for (int nt = 0; nt < 16; nt++)
#pragma unroll
            for (int q = 0; q < 4; q++) acc[nt][q] = 0.f;

        int rB = (lane & 7) + ((lane & 16) ? 8 : 0);
        int cB = (lane & 8) ? 16 : 0;
#pragma unroll
        for (int kc = 0; kc < 4; kc++) {
#pragma unroll
            for (int p = 0; p < 8; p++) {       // n-tile pairs
                uint32_t bfr[4];
                unsigned off = (p * 16 + rB) * 128 + kc * 32 + cB;
                ldmatrix_x4(bfr, sB_u[cur] + SW128(off));
                mma_bf16(acc[2 * p],     af[kc], bfr[0], bfr[1]);
                mma_bf16(acc[2 * p + 1], af[kc], bfr[2], bfr[3]);
            }
        }

        // epilogue: score = acc - 0.5*ksq, blockmax, pack bf16 into own stage rows
        int r_lo = wid * 16 + (lane >> 2);
        int r_hi = r_lo + 8;
        float rmax_lo = NEG_INF, rmax_hi = NEG_INF;
#pragma unroll
        for (int nt = 0; nt < 16; nt++) {
            int c = nt * 8 + (lane & 3) * 2;
            float2 kq = *reinterpret_cast<const float2*>(&sKsq[cur][c]);
            float s0 = acc[nt][0] - 0.5f * kq.x;
            float s1 = acc[nt][1] - 0.5f * kq.y;
            float s2 = acc[nt][2] - 0.5f * kq.x;
            float s3 = acc[nt][3] - 0.5f * kq.y;
            if (nBase + c     >= N) { s0 = NEG_INF; s2 = NEG_INF; }
            if (nBase + c + 1 >= N) { s1 = NEG_INF; s3 = NEG_INF; }
            rmax_lo = fmaxf(rmax_lo, fmaxf(s0, s1));
            rmax_hi = fmaxf(rmax_hi, fmaxf(s2, s3));
            __nv_bfloat162 p0 = __float22bfloat162_rn(make_float2(s0, s1));
            __nv_bfloat162 p1 = __float22bfloat162_rn(make_float2(s2, s3));
            unsigned o0 = r_lo * 256 + c * 2;
            unsigned o1 = r_hi * 256 + c * 2;
            *(uint32_t*)(&sStage[o0 ^ ((unsigned)(r_lo & 7) << 4)]) = *(uint32_t*)&p0;
            *(uint32_t*)(&sStage[o1 ^ ((unsigned)(r_hi & 7) << 4)]) = *(uint32_t*)&p1;
        }
        // quad-reduce row maxima (lanes l, l^1, l^2 share the row)
#pragma unroll
        for (int o = 1; o <= 2; o <<= 1) {
            rmax_lo = fmaxf(rmax_lo, __shfl_xor_sync(0xffffffffu, rmax_lo, o));
            rmax_hi = fmaxf(rmax_hi, __shfl_xor_sync(0xffffffffu, rmax_hi, o));
        }
        if ((lane & 3) == 0) {
            g_blockmax[(size_t)(rowBase + r_lo) * NBLK + blk] = rmax_lo;
            g_blockmax[(size_t)(rowBase + r_hi) * NBLK + blk] = rmax_hi;
        }
        __syncwarp();

        // per-warp copy of OWN 16 stage rows -> g_coarse (no CTA sync needed)
        int rbase = wid * 16;
#pragma unroll
        for (int rr = 0; rr < 8; rr++) {        // 2 rows per iteration
            int row = rbase + rr * 2 + (lane >> 4);
            int c16 = lane & 15;
            unsigned off = (unsigned)(row * 256 + c16 * 16) ^ ((unsigned)(row & 7) << 4);
            uint4 v = *(uint4*)(&sStage[off]);
            *reinterpret_cast<uint4*>(
                g_coarse + (size_t)(rowBase + row) * NPAD + nBase + c16 * 8) = v;
        }
        __syncthreads();                        // buffer `cur` free for it+2 prefetch
    }
}

// ---------------- Kernel 4: radix-threshold + exact refine top-50 ----------------
#define NTS 256
#define POOL2 1024
#define BLMAX 1024
#define MARGIN 1.5f      // covers bf16 input rounding + bf16 coarse storage error

__device__ __forceinline__ void bsort_desc(float* s, int* id, int m, int tid)
{
    for (int k = 2; k <= m; k <<= 1) {
        for (int j = k >> 1; j > 0; j >>= 1) {
            for (int i = tid; i < m; i += NTS) {
                int x = i ^ j;
                if (x > i) {
                    float a = s[i], b = s[x];
                    bool up = ((i & k) == 0);
                    if (up ? (a < b) : (a > b)) {
                        s[i] = b; s[x] = a;
                        int t = id[i]; id[i] = id[x]; id[x] = t;
                    }
                }
            }
            __syncthreads();
        }
    }
}

__global__ void __launch_bounds__(NTS) select2_kernel(
    const float* __restrict__ keys, const float* __restrict__ vals,
    float* __restrict__ outv, int B, int N, int NBLK, int NPAD)
{
    __shared__ unsigned ubm[MAXNBLK + 1];
    __shared__ int hist[256];
    __shared__ int sfx[257];
    __shared__ int blist[BLMAX];
    __shared__ float ps[POOL2];
    __shared__ int pi[POOL2];
    __shared__ __align__(8) float hrow[HDIM];
    __shared__ float wbuf[KNB], wvbuf[KNB];
    __shared__ unsigned sPfx;
    __shared__ int sK, bcnt, cnt;

    int row = blockIdx.x;
    int tid = threadIdx.x, lane = tid & 31, wid = tid >> 5;
    const float* BMrow = g_blockmax + (size_t)row * NBLK;
    const __nv_bfloat16* Crow = g_coarse + (size_t)row * NPAD;

    if (tid == 0) { sPfx = 0; sK = KNB; bcnt = 0; cnt = 0; }
    if (tid < HDIM) hrow[tid] = g_h[row * HDIM + tid];
    for (int j = tid; j < NBLK; j += NTS) {
        unsigned b = __float_as_uint(BMrow[j]);
        ubm[j] = (b & 0x80000000u) ? ~b : (b | 0x80000000u);
    }
    __syncthreads();

    // exact 50th-largest blockmax via 4-pass radix select (parallel suffix scan)
    for (int p = 3; p >= 0; p--) {
        hist[tid] = 0;                          // NTS == 256
        __syncthreads();
        unsigned pfx = sPfx;
        int K = sK;
        int sh = p * 8;
        unsigned maskhi = (p == 3) ? 0u : (0xFFFFFFFFu << (8 * (p + 1)));
        for (int j = tid; j < NBLK; j += NTS) {
            unsigned u = ubm[j];
            if ((u & maskhi) == pfx) atomicAdd(&hist[(u >> sh) & 255], 1);
        }
        __syncthreads();
        // suffix sums: sfx[t] = sum_{b>=t} hist[b]
        sfx[tid] = hist[tid];
        __syncthreads();
#pragma unroll
        for (int off = 1; off < 256; off <<= 1) {
            int v = (tid + off < 256) ? sfx[tid + off] : 0;
            __syncthreads();
            sfx[tid] += v;
            __syncthreads();
        }
        int s = sfx[tid];
        int snx = (tid < 255) ? sfx[tid + 1] : 0;
        if (s >= K && snx < K) {                // unique boundary bucket
            sPfx = pfx | ((unsigned)tid << sh);
            sK = K - snx;
        }
        __syncthreads();
    }
    unsigned Tu = sPfx;
    float Tf = (Tu & 0x80000000u) ? __uint_as_float(Tu & 0x7FFFFFFFu)
                                  : __uint_as_float(~Tu);
    float Tm = Tf - MARGIN;
    unsigned tb = __float_as_uint(Tm);
    unsigned um = (tb & 0x80000000u) ? ~tb : (tb | 0x80000000u);

    // surviving block list (coarse blockmax >= Tm); padded loop so all lanes
    // stay live for ballot (R12 hang root cause)
    int NBLKpad = (NBLK + NTS - 1) / NTS * NTS;
    for (int j = tid; j < NBLKpad; j += NTS) {
        bool pred = (j < NBLK) && (ubm[j] >= um);
        unsigned mask = __ballot_sync(0xffffffffu, pred);
        if (mask) {
            int leader = __ffs(mask) - 1;
            int basep = 0;
            if (lane == leader) basep = atomicAdd(&bcnt, __popc(mask));
            basep = __shfl_sync(0xffffffffu, basep, leader);
            if (pred) {
                int p = basep + __popc(mask & ((1u << lane) - 1u));
                if (p < BLMAX) blist[p] = j;
            }
        }
    }
    __syncthreads();
    int nb = bcnt < BLMAX ? bcnt : BLMAX;

    // scan surviving blocks' coarse bf16 scores, collect candidate ids
    for (int b = wid; b < nb; b += NTS / 32) {
        int base = blist[b] * 128;
#pragma unroll
        for (int q = 0; q < 4; q++) {
            int i = base + q * 32 + lane;
            float s = __bfloat162float(Crow[i]);     // padding cols are -inf
            bool pred = (s >= Tm);
            unsigned mask = __ballot_sync(0xffffffffu, pred);
            if (mask) {
                int leader = __ffs(mask) - 1;
                int basep = 0;
                if (lane == leader) basep = atomicAdd(&cnt, __popc(mask));
                basep = __shfl_sync(0xffffffffu, basep, leader);
                if (pred) {
                    int p = basep + __popc(mask & ((1u << lane) - 1u));
                    if (p < POOL2) pi[p] = i;
                }
            }
        }
    }
    __syncthreads();
    int c = cnt < POOL2 ? cnt : POOL2;

    // exact fp32 refine: warp per candidate (warp-uniform loop bound)
    for (int j = wid; j < c; j += NTS / 32) {
        int id = pi[j];
        float2 kv = reinterpret_cast<const float2*>(keys + (size_t)id * HDIM)[lane];
        float2 hv = *reinterpret_cast<const float2*>(hrow + 2 * lane);
        float d = kv.x * hv.x + kv.y * hv.y;
#pragma unroll
        for (int o = 16; o; o >>= 1) d += __shfl_xor_sync(0xffffffffu, d, o);
        if (lane == 0) ps[j] = d - 0.5f * g_ksq[id];
    }
    __syncthreads();

    int m = 64;
    while (m < c) m <<= 1;
    for (int i = c + tid; i < m; i += NTS) { ps[i] = NEG_INF; pi[i] = 0; }
    __syncthreads();
    bsort_desc(ps, pi, m, tid);

    if (tid < KNB) {
        float s = ps[tid];
        float d = fmaxf(g_hsq[row] - 2.0f * s, 0.0f);
        float w = 1.0f / (d + 1e-3f);
        wbuf[tid]  = w;
        wvbuf[tid] = w * vals[pi[tid]];
    }
    __syncthreads();
    if (tid == 0) {
        float ws = 0.f, wv = 0.f;
#pragma unroll
        for (int i = 0; i < KNB; i++) { ws += wbuf[i]; wv += wvbuf[i]; }
        outv[row] = wv / ws;
    }
}

// ---------------- launch ----------------
extern "C" void kernel_launch(void* const* d_in, const int* in_sizes, int n_in,
                              void* d_out, int out_size)
{
    const float* x    = (const float*)d_in[0];
    const float* W1   = (const float*)d_in[1];
    const float* b1   = (const float*)d_in[2];
    const float* Wp   = (const float*)d_in[3];
    const float* bp   = (const float*)d_in[4];
    const float* keys = (const float*)d_in[5];
    const float* vals = (const float*)d_in[6];
    float* out = (float*)d_out;

    int H = in_sizes[2];              // 64
    int S = in_sizes[1] / H;          // 256
    int B = in_sizes[0] / S;          // 1024
    int N = in_sizes[5] / H;          // 200000
    int NBLK = (N + 127) / 128;       // 1563
    int NPAD = NBLK * 128;            // 200064

    mlp_kernel<<<B, SDIM>>>(x, W1, b1, Wp, bp, out, B);
    kprep_kernel<<<(N + 7) / 8, 256>>>(keys, N);     // bf16 convert + ksq fused

    int STRIPS = 37;                                  // 37*8 = 296 CTAs = 1 wave @occ2
    int tilesPerCTA = (NBLK + STRIPS - 1) / STRIPS;   // 43
    dim3 g2(STRIPS, B / 128);
    tgemm_kernel<<<g2, 256>>>(B, N, NBLK, NPAD, tilesPerCTA);

    // output layout: policy [B,A] | value [B,1] | h [B,H]
    select2_kernel<<<B, NTS>>>(keys, vals, out + (size_t)B * ADIM, B, N, NBLK, NPAD);
}

// round 16
// speedup vs baseline: 8.5616x; 1.0407x over previous
#include <cuda_runtime.h>
#include <cuda_bf16.h>
#include <cstdint>
#include <cstddef>

// Problem dimensions (fixed by the dataset; grid sizes derived from in_sizes)
#define HDIM 64
#define SDIM 256
#define ADIM 18
#define MAXB 1024
#define MAXN 200000
#define MAXNBLK ((MAXN + 127) / 128)          // 1563
#define MAXNPAD (MAXNBLK * 128)               // 200064
#define NEG_INF (-3.4e38f)
#define KNB 50

// ---------------- scratch (device globals: allocation-free) ----------------
__device__ uint8_t g_coarse8[(size_t)MAXB * MAXNPAD];        // ~205 MB int8 coarse
__device__ __nv_bfloat16 g_kbf[(size_t)MAXN * HDIM];         // bf16 keys
__device__ float g_blockmax[(size_t)MAXB * MAXNBLK];         // ~6.4 MB
__device__ float g_h[MAXB * HDIM];
__device__ float g_hsq[MAXB];
__device__ float g_ksq[MAXN];

__device__ __forceinline__ uint32_t smem_u32(const void* p) {
    uint32_t a;
    asm("{ .reg .u64 t; cvta.to.shared.u64 t, %1; cvt.u32.u64 %0, t; }"
        : "=r"(a) : "l"(p));
    return a;
}
__device__ __forceinline__ void ldmatrix_x4(uint32_t* r, uint32_t addr) {
    asm volatile("ldmatrix.sync.aligned.m8n8.x4.shared.b16 {%0,%1,%2,%3}, [%4];"
                 : "=r"(r[0]), "=r"(r[1]), "=r"(r[2]), "=r"(r[3]) : "r"(addr));
}
__device__ __forceinline__ void mma_bf16(float* d, const uint32_t* a,
                                         uint32_t b0, uint32_t b1) {
    asm volatile(
        "mma.sync.aligned.m16n8k16.row.col.f32.bf16.bf16.f32 "
        "{%0,%1,%2,%3}, {%4,%5,%6,%7}, {%8,%9}, {%0,%1,%2,%3};"
        : "+f"(d[0]), "+f"(d[1]), "+f"(d[2]), "+f"(d[3])
        : "r"(a[0]), "r"(a[1]), "r"(a[2]), "r"(a[3]), "r"(b0), "r"(b1));
}
__device__ __forceinline__ void cp_async16(uint32_t dst, const void* src) {
    asm volatile("cp.async.ca.shared.global [%0], [%1], 16;"
                 :: "r"(dst), "l"(src) : "memory");
}
#define CP_COMMIT() asm volatile("cp.async.commit_group;" ::: "memory")
#define CP_WAIT(n)  asm volatile("cp.async.wait_group %0;" :: "n"(n) : "memory")
#define SW128(off) ((off) ^ (((off) >> 3) & 0x70))

// ---------------- Kernel 1: MLP (h, policy, hsq) ----------------
__global__ void __launch_bounds__(SDIM) mlp_kernel(
    const float* __restrict__ x, const float* __restrict__ W1,
    const float* __restrict__ b1, const float* __restrict__ Wp,
    const float* __restrict__ bp, float* __restrict__ out, int B)
{
    __shared__ float xs[SDIM];
    __shared__ float hs[HDIM];
    __shared__ float ps[4][HDIM];
    int row = blockIdx.x;
    int t = threadIdx.x;

    xs[t] = x[(size_t)row * SDIM + t];
    __syncthreads();

    int j = t & 63;
    int part = t >> 6;
    const float* w = W1 + (size_t)(part * 64) * HDIM + j;
    const float* xp = xs + part * 64;
    float acc = 0.f;
#pragma unroll 8
    for (int k = 0; k < 64; k++) acc = fmaf(xp[k], w[(size_t)k * HDIM], acc);
    ps[part][j] = acc;
    __syncthreads();

    if (t < HDIM) {
        float h = ps[0][t] + ps[1][t] + ps[2][t] + ps[3][t] + b1[t];
        h = fmaxf(h, 0.f);
        hs[t] = h;
        g_h[row * HDIM + t] = h;
        out[(size_t)B * (ADIM + 1) + (size_t)row * HDIM + t] = h;
        ps[0][t] = h * h;
    }
    __syncthreads();

    if (t == 0) {
        float s = 0.f;
        for (int i = 0; i < HDIM; i++) s += ps[0][i];
        g_hsq[row] = s;
    }
    if (t < ADIM) {
        float p = bp[t];
#pragma unroll
        for (int jj = 0; jj < HDIM; jj++) p = fmaf(hs[jj], Wp[jj * ADIM + t], p);
        out[(size_t)row * ADIM + t] = p;
    }
}

// ---------------- Kernel 2: keys fp32 -> bf16 + squared norms (fused) ----------------
__global__ void __launch_bounds__(256) kprep_kernel(const float* __restrict__ Kmem, int N)
{
    int gw = blockIdx.x * 8 + (threadIdx.x >> 5);   // key index
    int lane = threadIdx.x & 31;
    if (gw >= N) return;
    float2 v = reinterpret_cast<const float2*>(Kmem + (size_t)gw * HDIM)[lane];
    __nv_bfloat162 b = __float22bfloat162_rn(v);
    reinterpret_cast<__nv_bfloat162*>(g_kbf + (size_t)gw * HDIM)[lane] = b;
    float s = fmaf(v.x, v.x, v.y * v.y);
#pragma unroll
    for (int o = 16; o; o >>= 1) s += __shfl_xor_sync(0xffffffffu, s, o);
    if (lane == 0) g_ksq[gw] = s;
}

// ---------------- Kernel 3: HMMA bf16 coarse GEMM, int8 scores + blockmax ----------------
// s[b][n] = bf16dot(h_b,k_n) - 0.5*ksq[n];  q = min(255,(bmax-s)*8) (upper-bound code)
__global__ void __launch_bounds__(256, 2) tgemm_kernel(int B, int N, int NBLK,
                                                       int NPAD, int tilesPerCTA)
{
    __shared__ __align__(1024) uint8_t sA[128 * 128];         // 128 rows x 64 bf16, SW128
    __shared__ __align__(1024) uint8_t sB[2][128 * 128];      // double-buffered B tiles
    __shared__ __align__(16) float sKsq[2][128];
    __shared__ __align__(128) uint8_t sStage[128 * 128];      // int8 stage, warp-private rows

    int tid = threadIdx.x, wid = tid >> 5, lane = tid & 31;
    int rowBase = blockIdx.y * 128;
    int blk0 = blockIdx.x * tilesPerCTA;
    uint32_t sA_u = smem_u32(sA);
    uint32_t sB_u[2] = { smem_u32(sB[0]), smem_u32(sB[1]) };
    uint32_t sK_u[2] = { smem_u32(sKsq[0]), smem_u32(sKsq[1]) };

    auto prefetch = [&](int blk, int buf) {
        int nBase = blk * 128;
        int n = tid >> 1, half = tid & 1;
        int gn = nBase + n; if (gn > N - 1) gn = N - 1;     // pads masked in epilogue
        const __nv_bfloat16* src = g_kbf + (size_t)gn * HDIM + half * 32;
#pragma unroll
        for (int i = 0; i < 4; i++)
            cp_async16(sB_u[buf] + SW128((unsigned)(n * 128 + half * 64 + i * 16)),
                       src + i * 8);
        if (tid < 32) {
            int cb = nBase + tid * 4; if (cb > N - 4) cb = N - 4;  // N multiple of 4
            cp_async16(sK_u[buf] + tid * 16, g_ksq + cb);
        }
        CP_COMMIT();
    };

    // load + convert A tile (h rows fp32 -> bf16, SW128)
    {
        const float4* hr = reinterpret_cast<const float4*>(
            g_h + (size_t)(rowBase + (tid & 127)) * HDIM);
        if (tid < 128) {
#pragma unroll
            for (int i = 0; i < 8; i++) {
                float4 a = hr[2 * i], b = hr[2 * i + 1];
                uint32_t q[4];
                __nv_bfloat162 t0 = __float22bfloat162_rn(make_float2(a.x, a.y));
                __nv_bfloat162 t1 = __float22bfloat162_rn(make_float2(a.z, a.w));
                __nv_bfloat162 t2 = __float22bfloat162_rn(make_float2(b.x, b.y));
                __nv_bfloat162 t3 = __float22bfloat162_rn(make_float2(b.z, b.w));
                q[0] = *(uint32_t*)&t0; q[1] = *(uint32_t*)&t1;
                q[2] = *(uint32_t*)&t2; q[3] = *(uint32_t*)&t3;
                unsigned off = tid * 128 + i * 16;
                *(uint4*)(&sA[SW128(off)]) = *(uint4*)q;
            }
        }
    }
    prefetch(blk0, 0);
    __syncthreads();

    // preload A fragments (rows w*16..w*16+15, all 4 K16 chunks)
    uint32_t af[4][4];
    {
        int rA = wid * 16 + (lane & 15);
#pragma unroll
        for (int kc = 0; kc < 4; kc++) {
            unsigned off = rA * 128 + kc * 32 + (lane & 16);
            ldmatrix_x4(af[kc], sA_u + SW128(off));
        }
    }

    int nTiles = tilesPerCTA;
    if (blk0 + nTiles > NBLK) nTiles = NBLK - blk0;

    for (int it = 0; it < nTiles; it++) {
        int blk = blk0 + it;
        int nBase = blk * 128;
        int cur = it & 1;

        bool more = (it + 1 < nTiles);
        if (more) prefetch(blk + 1, cur ^ 1);
        if (more) { CP_WAIT(1); } else { CP_WAIT(0); }
        __syncthreads();

        float acc[16][4];
#pragma unroll
        for (int nt = 0; nt < 16; nt++)
#pragma unroll
            for (int q = 0; q < 4; q++) acc[nt][q] = 0.f;

        int rB = (lane & 7) + ((lane & 16) ? 8 : 0);
        int cB = (lane & 8) ? 16 : 0;
#pragma unroll
        for (int kc = 0; kc < 4; kc++) {
#pragma unroll
            for (int p = 0; p < 8; p++) {
                uint32_t bfr[4];
                unsigned off = (p * 16 + rB) * 128 + kc * 32 + cB;
                ldmatrix_x4(bfr, sB_u[cur] + SW128(off));
                mma_bf16(acc[2 * p],     af[kc], bfr[0], bfr[1]);
                mma_bf16(acc[2 * p + 1], af[kc], bfr[2], bfr[3]);
            }
        }

        // epilogue pass 1: scores (overwrite acc) + row maxima
        int r_lo = wid * 16 + (lane >> 2);
        int r_hi = r_lo + 8;
        float rmax_lo = NEG_INF, rmax_hi = NEG_INF;
#pragma unroll
        for (int nt = 0; nt < 16; nt++) {
            int c = nt * 8 + (lane & 3) * 2;
            float2 kq = *reinterpret_cast<const float2*>(&sKsq[cur][c]);
            float s0 = acc[nt][0] - 0.5f * kq.x;
            float s1 = acc[nt][1] - 0.5f * kq.y;
            float s2 = acc[nt][2] - 0.5f * kq.x;
            float s3 = acc[nt][3] - 0.5f * kq.y;
            if (nBase + c     >= N) { s0 = NEG_INF; s2 = NEG_INF; }
            if (nBase + c + 1 >= N) { s1 = NEG_INF; s3 = NEG_INF; }
            rmax_lo = fmaxf(rmax_lo, fmaxf(s0, s1));
            rmax_hi = fmaxf(rmax_hi, fmaxf(s2, s3));
            acc[nt][0] = s0; acc[nt][1] = s1; acc[nt][2] = s2; acc[nt][3] = s3;
        }
#pragma unroll
        for (int o = 1; o <= 2; o <<= 1) {
            rmax_lo = fmaxf(rmax_lo, __shfl_xor_sync(0xffffffffu, rmax_lo, o));
            rmax_hi = fmaxf(rmax_hi, __shfl_xor_sync(0xffffffffu, rmax_hi, o));
        }
        if ((lane & 3) == 0) {
            g_blockmax[(size_t)(rowBase + r_lo) * NBLK + blk] = rmax_lo;
            g_blockmax[(size_t)(rowBase + r_hi) * NBLK + blk] = rmax_hi;
        }

        // epilogue pass 2: int8 encode (q = floor((bmax - s)*8), clamp 255)
#pragma unroll
        for (int nt = 0; nt < 16; nt++) {
            int c = nt * 8 + (lane & 3) * 2;
            unsigned q0 = (unsigned)(int)fminf((rmax_lo - acc[nt][0]) * 8.0f, 255.0f);
            unsigned q1 = (unsigned)(int)fminf((rmax_lo - acc[nt][1]) * 8.0f, 255.0f);
            unsigned q2 = (unsigned)(int)fminf((rmax_hi - acc[nt][2]) * 8.0f, 255.0f);
            unsigned q3 = (unsigned)(int)fminf((rmax_hi - acc[nt][3]) * 8.0f, 255.0f);
            unsigned o0 = (unsigned)(r_lo * 128 + c) ^ ((unsigned)(r_lo & 7) << 4);
            unsigned o1 = (unsigned)(r_hi * 128 + c) ^ ((unsigned)(r_hi & 7) << 4);
            *(uint16_t*)(&sStage[o0]) = (uint16_t)(q0 | (q1 << 8));
            *(uint16_t*)(&sStage[o1]) = (uint16_t)(q2 | (q3 << 8));
        }
        __syncwarp();

        // per-warp copy of OWN 16 stage rows -> g_coarse8 (128 B per row)
#pragma unroll
        for (int rr = 0; rr < 4; rr++) {        // 4 rows per iteration
            int row = wid * 16 + rr * 4 + (lane >> 3);
            int g = lane & 7;                   // 16-B group within row
            unsigned off = (unsigned)(row * 128 + g * 16) ^ ((unsigned)(row & 7) << 4);
            uint4 v = *(uint4*)(&sStage[off]);
            *reinterpret_cast<uint4*>(
                g_coarse8 + (size_t)(rowBase + row) * NPAD + nBase + g * 16) = v;
        }
        __syncthreads();
    }
}

// ---------------- Kernel 4: 2-pass radix threshold + exact refine top-50 ----------------
#define NTS 256
#define UPB 7            // ceil(MAXNBLK / NTS)
#define POOL2 1024
#define BLMAX 1024
#define MARGIN 1.5f      // >= 2x bf16 dot error; 16-bit radix slack folded in via Tf_lb

__device__ __forceinline__ void bsort_desc(float* s, int* id, int m, int tid)
{
    for (int k = 2; k <= m; k <<= 1) {
        for (int j = k >> 1; j > 0; j >>= 1) {
            for (int i = tid; i < m; i += NTS) {
                int x = i ^ j;
                if (x > i) {
                    float a = s[i], b = s[x];
                    bool up = ((i & k) == 0);
                    if (up ? (a < b) : (a > b)) {
                        s[i] = b; s[x] = a;
                        int t = id[i]; id[i] = id[x]; id[x] = t;
                    }
                }
            }
            __syncthreads();
        }
    }
}

__global__ void __launch_bounds__(NTS) select2_kernel(
    const float* __restrict__ keys, const float* __restrict__ vals,
    float* __restrict__ outv, int B, int N, int NBLK, int NPAD)
{
    __shared__ float bmf[MAXNBLK + 1];
    __shared__ int hist[256];
    __shared__ int sfx[257];
    __shared__ int blist[BLMAX];
    __shared__ float ps[POOL2];
    __shared__ int pi[POOL2];
    __shared__ __align__(16) float hrow[HDIM];
    __shared__ float wbuf[KNB], wvbuf[KNB];
    __shared__ unsigned sPfx;
    __shared__ int sK, bcnt, cnt;

    int row = blockIdx.x;
    int tid = threadIdx.x, lane = tid & 31, wid = tid >> 5;
    const float* BMrow = g_blockmax + (size_t)row * NBLK;
    const uint8_t* Crow = g_coarse8 + (size_t)row * NPAD;

    if (tid == 0) { sPfx = 0; sK = KNB; bcnt = 0; cnt = 0; }
    if (tid < HDIM) hrow[tid] = g_h[row * HDIM + tid];

    // blockmaxes: registers (order-flipped) + smem float copy
    unsigned ur[UPB];
#pragma unroll
    for (int it = 0; it < UPB; it++) {
        int j = tid + it * NTS;
        float v = (j < NBLK) ? BMrow[j] : NEG_INF;
        if (j < NBLK) bmf[j] = v;
        unsigned b = __float_as_uint(v);
        ur[it] = (b & 0x80000000u) ? ~b : (b | 0x80000000u);
    }
    __syncthreads();

    // 50th-largest blockmax, upper 16 bits only (Tf_lb <= Tf; exactness kept)
#pragma unroll
    for (int p = 3; p >= 2; p--) {
        hist[tid] = 0;
        __syncthreads();
        unsigned pfx = sPfx;
        int K = sK;
        int sh = p * 8;
        unsigned maskhi = (p == 3) ? 0u : 0xFF000000u;
#pragma unroll
        for (int it = 0; it < UPB; it++) {
            unsigned u = ur[it];
            if ((u & maskhi) == pfx) atomicAdd(&hist[(u >> sh) & 255], 1);
        }
        __syncthreads();
        sfx[tid] = hist[tid];
        __syncthreads();
#pragma unroll
        for (int off = 1; off < 256; off <<= 1) {
            int v = (tid + off < 256) ? sfx[tid + off] : 0;
            __syncthreads();
            sfx[tid] += v;
            __syncthreads();
        }
        int s = sfx[tid];
        int snx = (tid < 255) ? sfx[tid + 1] : 0;
        if (s >= K && snx < K) {
            sPfx = pfx | ((unsigned)tid << sh);
            sK = K - snx;
        }
        __syncthreads();
    }
    unsigned Tu = sPfx;
    float Tf = (Tu & 0x80000000u) ? __uint_as_float(Tu & 0x7FFFFFFFu)
                                  : __uint_as_float(~Tu);
    float Tm = Tf - MARGIN;
    unsigned tb = __float_as_uint(Tm);
    unsigned um = (tb & 0x80000000u) ? ~tb : (tb | 0x80000000u);

    // surviving block list (fixed trip count: all lanes live for ballot)
#pragma unroll
    for (int it = 0; it < UPB; it++) {
        int j = tid + it * NTS;
        bool pred = (j < NBLK) && (ur[it] >= um);
        unsigned mask = __ballot_sync(0xffffffffu, pred);
        if (mask) {
            int leader = __ffs(mask) - 1;
            int basep = 0;
            if (lane == leader) basep = atomicAdd(&bcnt, __popc(mask));
            basep = __shfl_sync(0xffffffffu, basep, leader);
            if (pred) {
                int p = basep + __popc(mask & ((1u << lane) - 1u));
                if (p < BLMAX) blist[p] = j;
            }
        }
    }
    __syncthreads();
    int nb = bcnt < BLMAX ? bcnt : BLMAX;

    // scan surviving blocks: one 128B load/warp, decode ub = bmax - q/8
    for (int b = wid; b < nb; b += NTS / 32) {
        int blk = blist[b];
        int base = blk * 128;
        float bx = bmf[blk];
        uint32_t u4 = reinterpret_cast<const uint32_t*>(Crow + base)[lane];
#pragma unroll
        for (int sub = 0; sub < 4; sub++) {
            int i = base + lane * 4 + sub;
            float ub = bx - 0.125f * (float)((u4 >> (8 * sub)) & 255u);
            bool pred = (ub >= Tm) && (i < N);
            unsigned mask = __ballot_sync(0xffffffffu, pred);
            if (mask) {
                int leader = __ffs(mask) - 1;
                int basep = 0;
                if (lane == leader) basep = atomicAdd(&cnt, __popc(mask));
                basep = __shfl_sync(0xffffffffu, basep, leader);
                if (pred) {
                    int p = basep + __popc(mask & ((1u << lane) - 1u));
                    if (p < POOL2) pi[p] = i;
                }
            }
        }
    }
    __syncthreads();
    int c = cnt < POOL2 ? cnt : POOL2;

    // exact fp32 refine: 2 candidates per warp (half-warp each)
    int half = lane >> 4, hl = lane & 15;
    for (int j = wid * 2; j < c; j += 2 * (NTS / 32)) {
        int jj = j + half;
        int id = pi[(jj < c) ? jj : j];
        float4 kv = reinterpret_cast<const float4*>(keys + (size_t)id * HDIM)[hl];
        float4 hv = reinterpret_cast<const float4*>(hrow)[hl];
        float d = kv.x * hv.x + kv.y * hv.y + kv.z * hv.z + kv.w * hv.w;
#pragma unroll
        for (int o = 8; o; o >>= 1) d += __shfl_xor_sync(0xffffffffu, d, o);
        if (hl == 0 && jj < c) ps[jj] = d - 0.5f * g_ksq[id];
    }
    __syncthreads();

    int m = 64;
    while (m < c) m <<= 1;
    for (int i = c + tid; i < m; i += NTS) { ps[i] = NEG_INF; pi[i] = 0; }
    __syncthreads();
    bsort_desc(ps, pi, m, tid);

    if (tid < KNB) {
        float s = ps[tid];
        float d = fmaxf(g_hsq[row] - 2.0f * s, 0.0f);
        float w = 1.0f / (d + 1e-3f);
        wbuf[tid]  = w;
        wvbuf[tid] = w * vals[pi[tid]];
    }
    __syncthreads();
    if (tid == 0) {
        float ws = 0.f, wv = 0.f;
#pragma unroll
        for (int i = 0; i < KNB; i++) { ws += wbuf[i]; wv += wvbuf[i]; }
        outv[row] = wv / ws;
    }
}

// ---------------- launch ----------------
extern "C" void kernel_launch(void* const* d_in, const int* in_sizes, int n_in,
                              void* d_out, int out_size)
{
    const float* x    = (const float*)d_in[0];
    const float* W1   = (const float*)d_in[1];
    const float* b1   = (const float*)d_in[2];
    const float* Wp   = (const float*)d_in[3];
    const float* bp   = (const float*)d_in[4];
    const float* keys = (const float*)d_in[5];
    const float* vals = (const float*)d_in[6];
    float* out = (float*)d_out;

    int H = in_sizes[2];              // 64
    int S = in_sizes[1] / H;          // 256
    int B = in_sizes[0] / S;          // 1024
    int N = in_sizes[5] / H;          // 200000
    int NBLK = (N + 127) / 128;       // 1563
    int NPAD = NBLK * 128;            // 200064

    mlp_kernel<<<B, SDIM>>>(x, W1, b1, Wp, bp, out, B);
    kprep_kernel<<<(N + 7) / 8, 256>>>(keys, N);     // bf16 convert + ksq fused

    int STRIPS = 37;                                  // 37*8 = 296 CTAs = 1 wave @occ2
    int tilesPerCTA = (NBLK + STRIPS - 1) / STRIPS;   // 43
    dim3 g2(STRIPS, B / 128);
    tgemm_kernel<<<g2, 256>>>(B, N, NBLK, NPAD, tilesPerCTA);

    // output layout: policy [B,A] | value [B,1] | h [B,H]
    select2_kernel<<<B, NTS>>>(keys, vals, out + (size_t)B * ADIM, B, N, NBLK, NPAD);
}

// round 17
// speedup vs baseline: 9.2320x; 1.0783x over previous
#include <cuda_runtime.h>
#include <cuda_bf16.h>
#include <cstdint>
#include <cstddef>

// Problem dimensions (fixed by the dataset; grid sizes derived from in_sizes)
#define HDIM 64
#define SDIM 256
#define ADIM 18
#define MAXB 1024
#define MAXN 200000
#define MAXNBLK ((MAXN + 127) / 128)          // 1563
#define MAXNPAD (MAXNBLK * 128)               // 200064
#define NEG_INF (-3.4e38f)
#define KNB 50

// ---------------- scratch (device globals: allocation-free) ----------------
__device__ uint8_t g_coarse8[(size_t)MAXB * MAXNPAD];        // ~205 MB int8 coarse
__device__ __nv_bfloat16 g_kbf[(size_t)MAXN * HDIM];         // bf16 keys
__device__ float g_blockmaxT[(size_t)MAXNBLK * MAXB];        // [blk][row], coalesced writes
__device__ float g_h[MAXB * HDIM];
__device__ float g_hsq[MAXB];
__device__ float g_ksq[MAXN];

__device__ __forceinline__ uint32_t smem_u32(const void* p) {
    uint32_t a;
    asm("{ .reg .u64 t; cvta.to.shared.u64 t, %1; cvt.u32.u64 %0, t; }"
        : "=r"(a) : "l"(p));
    return a;
}
__device__ __forceinline__ void ldmatrix_x4(uint32_t* r, uint32_t addr) {
    asm volatile("ldmatrix.sync.aligned.m8n8.x4.shared.b16 {%0,%1,%2,%3}, [%4];"
                 : "=r"(r[0]), "=r"(r[1]), "=r"(r[2]), "=r"(r[3]) : "r"(addr));
}
__device__ __forceinline__ void mma_bf16(float* d, const uint32_t* a,
                                         uint32_t b0, uint32_t b1) {
    asm volatile(
        "mma.sync.aligned.m16n8k16.row.col.f32.bf16.bf16.f32 "
        "{%0,%1,%2,%3}, {%4,%5,%6,%7}, {%8,%9}, {%0,%1,%2,%3};"
        : "+f"(d[0]), "+f"(d[1]), "+f"(d[2]), "+f"(d[3])
        : "r"(a[0]), "r"(a[1]), "r"(a[2]), "r"(a[3]), "r"(b0), "r"(b1));
}
__device__ __forceinline__ void cp_async16(uint32_t dst, const void* src) {
    asm volatile("cp.async.ca.shared.global [%0], [%1], 16;"
                 :: "r"(dst), "l"(src) : "memory");
}
#define CP_COMMIT() asm volatile("cp.async.commit_group;" ::: "memory")
#define CP_WAIT(n)  asm volatile("cp.async.wait_group %0;" :: "n"(n) : "memory")
#define SW128(off) ((off) ^ (((off) >> 3) & 0x70))

// ---------------- Kernel 1: MLP (h, policy, hsq) ----------------
__global__ void __launch_bounds__(SDIM) mlp_kernel(
    const float* __restrict__ x, const float* __restrict__ W1,
    const float* __restrict__ b1, const float* __restrict__ Wp,
    const float* __restrict__ bp, float* __restrict__ out, int B)
{
    __shared__ float xs[SDIM];
    __shared__ float hs[HDIM];
    __shared__ float ps[4][HDIM];
    int row = blockIdx.x;
    int t = threadIdx.x;

    xs[t] = x[(size_t)row * SDIM + t];
    __syncthreads();

    int j = t & 63;
    int part = t >> 6;
    const float* w = W1 + (size_t)(part * 64) * HDIM + j;
    const float* xp = xs + part * 64;
    float acc = 0.f;
#pragma unroll 8
    for (int k = 0; k < 64; k++) acc = fmaf(xp[k], w[(size_t)k * HDIM], acc);
    ps[part][j] = acc;
    __syncthreads();

    if (t < HDIM) {
        float h = ps[0][t] + ps[1][t] + ps[2][t] + ps[3][t] + b1[t];
        h = fmaxf(h, 0.f);
        hs[t] = h;
        g_h[row * HDIM + t] = h;
        out[(size_t)B * (ADIM + 1) + (size_t)row * HDIM + t] = h;
        ps[0][t] = h * h;
    }
    __syncthreads();

    if (t == 0) {
        float s = 0.f;
        for (int i = 0; i < HDIM; i++) s += ps[0][i];
        g_hsq[row] = s;
    }
    if (t < ADIM) {
        float p = bp[t];
#pragma unroll
        for (int jj = 0; jj < HDIM; jj++) p = fmaf(hs[jj], Wp[jj * ADIM + t], p);
        out[(size_t)row * ADIM + t] = p;
    }
}

// ---------------- Kernel 2: keys fp32 -> bf16 + squared norms (fused) ----------------
__global__ void __launch_bounds__(256) kprep_kernel(const float* __restrict__ Kmem, int N)
{
    int gw = blockIdx.x * 8 + (threadIdx.x >> 5);   // key index
    int lane = threadIdx.x & 31;
    if (gw >= N) return;
    float2 v = reinterpret_cast<const float2*>(Kmem + (size_t)gw * HDIM)[lane];
    __nv_bfloat162 b = __float22bfloat162_rn(v);
    reinterpret_cast<__nv_bfloat162*>(g_kbf + (size_t)gw * HDIM)[lane] = b;
    float s = fmaf(v.x, v.x, v.y * v.y);
#pragma unroll
    for (int o = 16; o; o >>= 1) s += __shfl_xor_sync(0xffffffffu, s, o);
    if (lane == 0) g_ksq[gw] = s;
}

// ---------------- Kernel 3: HMMA bf16 coarse GEMM (2-D warp tiling) ----------------
// s[b][n] = bf16dot(h_b,k_n) - 0.5*ksq[n];  q = min(255,(bmax-s)*8) (upper-bound code)
// warp w: rows (w&3)*32..+31 (2 m-tiles) x cols (w>>2)*64..+63 (8 n-tiles)
__global__ void __launch_bounds__(256, 2) tgemm_kernel(int B, int N, int NBLK,
                                                       int NPAD, int tilesPerCTA)
{
    __shared__ __align__(1024) uint8_t sA[128 * 128];         // 128 rows x 64 bf16, SW128
    __shared__ __align__(1024) uint8_t sB[2][128 * 128];      // double-buffered B tiles
    __shared__ __align__(16) float sKsq[2][128];
    __shared__ __align__(128) uint8_t sStage[128 * 128];      // int8 stage
    __shared__ float sRmax[128][2];
    __shared__ float sBmax[128];

    int tid = threadIdx.x, wid = tid >> 5, lane = tid & 31;
    int mh = wid & 3, ch = wid >> 2;
    int rowBase = blockIdx.y * 128;
    int blk0 = blockIdx.x * tilesPerCTA;
    uint32_t sA_u = smem_u32(sA);
    uint32_t sB_u[2] = { smem_u32(sB[0]), smem_u32(sB[1]) };
    uint32_t sK_u[2] = { smem_u32(sKsq[0]), smem_u32(sKsq[1]) };

    auto prefetch = [&](int blk, int buf) {
        int nBase = blk * 128;
        int n = tid >> 1, half = tid & 1;
        int gn = nBase + n; if (gn > N - 1) gn = N - 1;     // pads masked in epilogue
        const __nv_bfloat16* src = g_kbf + (size_t)gn * HDIM + half * 32;
#pragma unroll
        for (int i = 0; i < 4; i++)
            cp_async16(sB_u[buf] + SW128((unsigned)(n * 128 + half * 64 + i * 16)),
                       src + i * 8);
        if (tid < 32) {
            int cb = nBase + tid * 4; if (cb > N - 4) cb = N - 4;  // N multiple of 4
            cp_async16(sK_u[buf] + tid * 16, g_ksq + cb);
        }
        CP_COMMIT();
    };

    // load + convert A tile (h rows fp32 -> bf16, SW128)
    {
        const float4* hr = reinterpret_cast<const float4*>(
            g_h + (size_t)(rowBase + (tid & 127)) * HDIM);
        if (tid < 128) {
#pragma unroll
            for (int i = 0; i < 8; i++) {
                float4 a = hr[2 * i], b = hr[2 * i + 1];
                uint32_t q[4];
                __nv_bfloat162 t0 = __float22bfloat162_rn(make_float2(a.x, a.y));
                __nv_bfloat162 t1 = __float22bfloat162_rn(make_float2(a.z, a.w));
                __nv_bfloat162 t2 = __float22bfloat162_rn(make_float2(b.x, b.y));
                __nv_bfloat162 t3 = __float22bfloat162_rn(make_float2(b.z, b.w));
                q[0] = *(uint32_t*)&t0; q[1] = *(uint32_t*)&t1;
                q[2] = *(uint32_t*)&t2; q[3] = *(uint32_t*)&t3;
                unsigned off = tid * 128 + i * 16;
                *(uint4*)(&sA[SW128(off)]) = *(uint4*)q;
            }
        }
    }
    prefetch(blk0, 0);
    __syncthreads();

    // preload A fragments: 2 m-tiles x 4 K16 chunks — fixed per CTA
    uint32_t af[2][4][4];
#pragma unroll
    for (int mt = 0; mt < 2; mt++) {
        int rA = mh * 32 + mt * 16 + (lane & 15);
#pragma unroll
        for (int kc = 0; kc < 4; kc++) {
            unsigned off = rA * 128 + kc * 32 + (lane & 16);
            ldmatrix_x4(af[mt][kc], sA_u + SW128(off));
        }
    }

    int nTiles = tilesPerCTA;
    if (blk0 + nTiles > NBLK) nTiles = NBLK - blk0;

    for (int it = 0; it < nTiles; it++) {
        int blk = blk0 + it;
        int nBase = blk * 128;
        int cur = it & 1;
        bool lastTile = (blk == NBLK - 1) && (N < NPAD);

        bool more = (it + 1 < nTiles);
        if (more) prefetch(blk + 1, cur ^ 1);
        if (more) { CP_WAIT(1); } else { CP_WAIT(0); }
        __syncthreads();

        float acc[2][8][4];
#pragma unroll
        for (int mt = 0; mt < 2; mt++)
#pragma unroll
            for (int nt = 0; nt < 8; nt++)
#pragma unroll
                for (int q = 0; q < 4; q++) acc[mt][nt][q] = 0.f;

        int rB = (lane & 7) + ((lane & 16) ? 8 : 0);
        int cB = (lane & 8) ? 16 : 0;
#pragma unroll
        for (int kc = 0; kc < 4; kc++) {
#pragma unroll
            for (int p = 0; p < 4; p++) {       // n-tile pairs in own 64-col half
                uint32_t bfr[4];
                unsigned off = (ch * 64 + p * 16 + rB) * 128 + kc * 32 + cB;
                ldmatrix_x4(bfr, sB_u[cur] + SW128(off));
                mma_bf16(acc[0][2 * p],     af[0][kc], bfr[0], bfr[1]);
                mma_bf16(acc[0][2 * p + 1], af[0][kc], bfr[2], bfr[3]);
                mma_bf16(acc[1][2 * p],     af[1][kc], bfr[0], bfr[1]);
                mma_bf16(acc[1][2 * p + 1], af[1][kc], bfr[2], bfr[3]);
            }
        }

        // pass 1: scores (into acc) + per-row 64-col maxima -> sRmax[row][ch]
        int qrow = lane >> 2, qcol = (lane & 3) * 2;
#pragma unroll
        for (int mt = 0; mt < 2; mt++) {
            float rlo = NEG_INF, rhi = NEG_INF;
#pragma unroll
            for (int nt = 0; nt < 8; nt++) {
                int c = ch * 64 + nt * 8 + qcol;
                float2 kq = *reinterpret_cast<const float2*>(&sKsq[cur][c]);
                float s0 = acc[mt][nt][0] - 0.5f * kq.x;
                float s1 = acc[mt][nt][1] - 0.5f * kq.y;
                float s2 = acc[mt][nt][2] - 0.5f * kq.x;
                float s3 = acc[mt][nt][3] - 0.5f * kq.y;
                if (lastTile) {                  // uniform branch, 1/1563 tiles
                    if (nBase + c     >= N) { s0 = NEG_INF; s2 = NEG_INF; }
                    if (nBase + c + 1 >= N) { s1 = NEG_INF; s3 = NEG_INF; }
                }
                rlo = fmaxf(rlo, fmaxf(s0, s1));
                rhi = fmaxf(rhi, fmaxf(s2, s3));
                acc[mt][nt][0] = s0; acc[mt][nt][1] = s1;
                acc[mt][nt][2] = s2; acc[mt][nt][3] = s3;
            }
#pragma unroll
            for (int o = 1; o <= 2; o <<= 1) {
                rlo = fmaxf(rlo, __shfl_xor_sync(0xffffffffu, rlo, o));
                rhi = fmaxf(rhi, __shfl_xor_sync(0xffffffffu, rhi, o));
            }
            if ((lane & 3) == 0) {
                sRmax[mh * 32 + mt * 16 + qrow][ch]     = rlo;
                sRmax[mh * 32 + mt * 16 + qrow + 8][ch] = rhi;
            }
        }
        __syncthreads();

        // combine col-halves; coalesced blockmax store ([blk][row] layout)
        if (tid < 128) {
            float bm = fmaxf(sRmax[tid][0], sRmax[tid][1]);
            g_blockmaxT[(size_t)blk * B + rowBase + tid] = bm;
            sBmax[tid] = bm;
        }
        __syncthreads();

        // pass 2: int8 encode (q = floor((bmax - s)*8), clamp 255) into stage
#pragma unroll
        for (int mt = 0; mt < 2; mt++) {
            int rl = mh * 32 + mt * 16 + qrow, rh = rl + 8;
            float bl = sBmax[rl], bh = sBmax[rh];
#pragma unroll
            for (int nt = 0; nt < 8; nt++) {
                int c = ch * 64 + nt * 8 + qcol;
                unsigned q0 = (unsigned)(int)fminf((bl - acc[mt][nt][0]) * 8.0f, 255.0f);
                unsigned q1 = (unsigned)(int)fminf((bl - acc[mt][nt][1]) * 8.0f, 255.0f);
                unsigned q2 = (unsigned)(int)fminf((bh - acc[mt][nt][2]) * 8.0f, 255.0f);
                unsigned q3 = (unsigned)(int)fminf((bh - acc[mt][nt][3]) * 8.0f, 255.0f);
                unsigned o0 = (unsigned)(rl * 128 + c) ^ ((unsigned)(rl & 7) << 4);
                unsigned o1 = (unsigned)(rh * 128 + c) ^ ((unsigned)(rh & 7) << 4);
                *(uint16_t*)(&sStage[o0]) = (uint16_t)(q0 | (q1 << 8));
                *(uint16_t*)(&sStage[o1]) = (uint16_t)(q2 | (q3 << 8));
            }
        }
        __syncthreads();

        // CTA copy stage -> g_coarse8 (128 rows x 128 B, coalesced uint4)
        for (int j = tid; j < 128 * 8; j += 256) {
            int row = j >> 3, g = j & 7;
            unsigned off = (unsigned)(row * 128 + g * 16) ^ ((unsigned)(row & 7) << 4);
            uint4 v = *(uint4*)(&sStage[off]);
            *reinterpret_cast<uint4*>(
                g_coarse8 + (size_t)(rowBase + row) * NPAD + nBase + g * 16) = v;
        }
        __syncthreads();
    }
}

// ---------------- Kernel 4: 2-pass radix threshold + exact refine top-50 ----------------
#define NTS 256
#define UPB 7            // ceil(MAXNBLK / NTS)
#define POOL2 1024
#define BLMAX 1024
#define MARGIN 1.5f      // >= 2x bf16 dot error; 16-bit radix slack folded in via Tf_lb

__device__ __forceinline__ void bsort_desc(float* s, int* id, int m, int tid)
{
    for (int k = 2; k <= m; k <<= 1) {
        for (int j = k >> 1; j > 0; j >>= 1) {
            for (int i = tid; i < m; i += NTS) {
                int x = i ^ j;
                if (x > i) {
                    float a = s[i], b = s[x];
                    bool up = ((i & k) == 0);
                    if (up ? (a < b) : (a > b)) {
                        s[i] = b; s[x] = a;
                        int t = id[i]; id[i] = id[x]; id[x] = t;
                    }
                }
            }
            __syncthreads();
        }
    }
}

__global__ void __launch_bounds__(NTS) select2_kernel(
    const float* __restrict__ keys, const float* __restrict__ vals,
    float* __restrict__ outv, int B, int N, int NBLK, int NPAD)
{
    __shared__ float bmf[MAXNBLK + 1];
    __shared__ int hist[256];
    __shared__ int sfx[257];
    __shared__ int blist[BLMAX];
    __shared__ float ps[POOL2];
    __shared__ int pi[POOL2];
    __shared__ __align__(16) float hrow[HDIM];
    __shared__ float wbuf[KNB], wvbuf[KNB];
    __shared__ unsigned sPfx;
    __shared__ int sK, bcnt, cnt;

    int row = blockIdx.x;
    int tid = threadIdx.x, lane = tid & 31, wid = tid >> 5;
    const uint8_t* Crow = g_coarse8 + (size_t)row * NPAD;

    if (tid == 0) { sPfx = 0; sK = KNB; bcnt = 0; cnt = 0; }
    if (tid < HDIM) hrow[tid] = g_h[row * HDIM + tid];

    // blockmaxes (transposed layout): registers (order-flipped) + smem copy
    unsigned ur[UPB];
#pragma unroll
    for (int it = 0; it < UPB; it++) {
        int j = tid + it * NTS;
        float v = (j < NBLK) ? g_blockmaxT[(size_t)j * B + row] : NEG_INF;
        if (j < NBLK) bmf[j] = v;
        unsigned b = __float_as_uint(v);
        ur[it] = (b & 0x80000000u) ? ~b : (b | 0x80000000u);
    }
    __syncthreads();

    // 50th-largest blockmax, upper 16 bits only (Tf_lb <= Tf; exactness kept)
#pragma unroll
    for (int p = 3; p >= 2; p--) {
        hist[tid] = 0;
        __syncthreads();
        unsigned pfx = sPfx;
        int K = sK;
        int sh = p * 8;
        unsigned maskhi = (p == 3) ? 0u : 0xFF000000u;
#pragma unroll
        for (int it = 0; it < UPB; it++) {
            unsigned u = ur[it];
            if ((u & maskhi) == pfx) atomicAdd(&hist[(u >> sh) & 255], 1);
        }
        __syncthreads();
        sfx[tid] = hist[tid];
        __syncthreads();
#pragma unroll
        for (int off = 1; off < 256; off <<= 1) {
            int v = (tid + off < 256) ? sfx[tid + off] : 0;
            __syncthreads();
            sfx[tid] += v;
            __syncthreads();
        }
        int s = sfx[tid];
        int snx = (tid < 255) ? sfx[tid + 1] : 0;
        if (s >= K && snx < K) {
            sPfx = pfx | ((unsigned)tid << sh);
            sK = K - snx;
        }
        __syncthreads();
    }
    unsigned Tu = sPfx;
    float Tf = (Tu & 0x80000000u) ? __uint_as_float(Tu & 0x7FFFFFFFu)
                                  : __uint_as_float(~Tu);
    float Tm = Tf - MARGIN;
    unsigned tb = __float_as_uint(Tm);
    unsigned um = (tb & 0x80000000u) ? ~tb : (tb | 0x80000000u);

    // surviving block list (fixed trip count: all lanes live for ballot)
#pragma unroll
    for (int it = 0; it < UPB; it++) {
        int j = tid + it * NTS;
        bool pred = (j < NBLK) && (ur[it] >= um);
        unsigned mask = __ballot_sync(0xffffffffu, pred);
        if (mask) {
            int leader = __ffs(mask) - 1;
            int basep = 0;
            if (lane == leader) basep = atomicAdd(&bcnt, __popc(mask));
            basep = __shfl_sync(0xffffffffu, basep, leader);
            if (pred) {
                int p = basep + __popc(mask & ((1u << lane) - 1u));
                if (p < BLMAX) blist[p] = j;
            }
        }
    }
    __syncthreads();
    int nb = bcnt < BLMAX ? bcnt : BLMAX;

    // scan surviving blocks: one 128B load/warp, decode ub = bmax - q/8
    for (int b = wid; b < nb; b += NTS / 32) {
        int blk = blist[b];
        int base = blk * 128;
        float bx = bmf[blk];
        uint32_t u4 = reinterpret_cast<const uint32_t*>(Crow + base)[lane];
#pragma unroll
        for (int sub = 0; sub < 4; sub++) {
            int i = base + lane * 4 + sub;
            float ub = bx - 0.125f * (float)((u4 >> (8 * sub)) & 255u);
            bool pred = (ub >= Tm) && (i < N);
            unsigned mask = __ballot_sync(0xffffffffu, pred);
            if (mask) {
                int leader = __ffs(mask) - 1;
                int basep = 0;
                if (lane == leader) basep = atomicAdd(&cnt, __popc(mask));
                basep = __shfl_sync(0xffffffffu, basep, leader);
                if (pred) {
                    int p = basep + __popc(mask & ((1u << lane) - 1u));
                    if (p < POOL2) pi[p] = i;
                }
            }
        }
    }
    __syncthreads();
    int c = cnt < POOL2 ? cnt : POOL2;

    // exact fp32 refine: 2 candidates per warp (half-warp each)
    int half = lane >> 4, hl = lane & 15;
    for (int j = wid * 2; j < c; j += 2 * (NTS / 32)) {
        int jj = j + half;
        int id = pi[(jj < c) ? jj : j];
        float4 kv = reinterpret_cast<const float4*>(keys + (size_t)id * HDIM)[hl];
        float4 hv = reinterpret_cast<const float4*>(hrow)[hl];
        float d = kv.x * hv.x + kv.y * hv.y + kv.z * hv.z + kv.w * hv.w;
#pragma unroll
        for (int o = 8; o; o >>= 1) d += __shfl_xor_sync(0xffffffffu, d, o);
        if (hl == 0 && jj < c) ps[jj] = d - 0.5f * g_ksq[id];
    }
    __syncthreads();

    int m = 64;
    while (m < c) m <<= 1;
    for (int i = c + tid; i < m; i += NTS) { ps[i] = NEG_INF; pi[i] = 0; }
    __syncthreads();
    bsort_desc(ps, pi, m, tid);

    if (tid < KNB) {
        float s = ps[tid];
        float d = fmaxf(g_hsq[row] - 2.0f * s, 0.0f);
        float w = 1.0f / (d + 1e-3f);
        wbuf[tid]  = w;
        wvbuf[tid] = w * vals[pi[tid]];
    }
    __syncthreads();
    if (tid == 0) {
        float ws = 0.f, wv = 0.f;
#pragma unroll
        for (int i = 0; i < KNB; i++) { ws += wbuf[i]; wv += wvbuf[i]; }
        outv[row] = wv / ws;
    }
}

// ---------------- launch ----------------
extern "C" void kernel_launch(void* const* d_in, const int* in_sizes, int n_in,
                              void* d_out, int out_size)
{
    const float* x    = (const float*)d_in[0];
    const float* W1   = (const float*)d_in[1];
    const float* b1   = (const float*)d_in[2];
    const float* Wp   = (const float*)d_in[3];
    const float* bp   = (const float*)d_in[4];
    const float* keys = (const float*)d_in[5];
    const float* vals = (const float*)d_in[6];
    float* out = (float*)d_out;

    int H = in_sizes[2];              // 64
    int S = in_sizes[1] / H;          // 256
    int B = in_sizes[0] / S;          // 1024
    int N = in_sizes[5] / H;          // 200000
    int NBLK = (N + 127) / 128;       // 1563
    int NPAD = NBLK * 128;            // 200064

    mlp_kernel<<<B, SDIM>>>(x, W1, b1, Wp, bp, out, B);
    kprep_kernel<<<(N + 7) / 8, 256>>>(keys, N);     // bf16 convert + ksq fused

    int STRIPS = 37;                                  // 37*8 = 296 CTAs = 1 wave @occ2
    int tilesPerCTA = (NBLK + STRIPS - 1) / STRIPS;   // 43
    dim3 g2(STRIPS, B / 128);
    tgemm_kernel<<<g2, 256>>>(B, N, NBLK, NPAD, tilesPerCTA);

    // output layout: policy [B,A] | value [B,1] | h [B,H]
    select2_kernel<<<B, NTS>>>(keys, vals, out + (size_t)B * ADIM, B, N, NBLK, NPAD);
}